// round 2
// baseline (speedup 1.0000x reference)
#include <cuda_runtime.h>

// Elman RNN, persistent-kernel formulation.
// grid = 128 CTAs: p = blockIdx>>6 picks batch half (128 rows), q = blockIdx&63
// picks 8 output columns. Each CTA keeps its [Wh;Wx] column slice in smem for
// the whole run. Recurrent state ping-pongs through __device__ global memory
// with .cg loads/stores (L1 is not coherent across SMs). One two-level atomic
// grid barrier per timestep.

#define NCTA 128
#define TPB  256

#define Bb 256
#define Tt 512
#define Ff 256
#define Hh 512
#define KTOT 768          // Hh + Ff (fused K: recurrent part then input part)
#define NTILE 24          // KTOT / 32
#define KTILE 32
#define MROWS 128         // batch rows per group
#define SA_STRIDE 36      // padded row stride (floats) for the A tile

__device__ float    g_h[2][Bb * Hh];   // ping-pong hidden state, zero-init by CUDA
__device__ unsigned g_cnt[8 * 64];     // 8 arrival cells, 256B apart
__device__ unsigned g_master;
__device__ unsigned g_gen;
__device__ unsigned g_exit;

__device__ __forceinline__ void grid_barrier(int bar) {
    __syncthreads();
    if (threadIdx.x == 0) {
        __threadfence();
        unsigned cell = blockIdx.x & 7u;
        unsigned prev = atomicAdd(&g_cnt[cell * 64], 1u);
        if (prev == 16u * (unsigned)(bar + 1) - 1u) {        // last in cell
            unsigned m = atomicAdd(&g_master, 1u);
            if (m == 8u * (unsigned)(bar + 1) - 1u) {        // last cell
                atomicExch(&g_gen, (unsigned)(bar + 1));     // release
            }
        }
        while (*((volatile unsigned*)&g_gen) < (unsigned)(bar + 1)) { }
        __threadfence();
    }
    __syncthreads();
}

__global__ void __launch_bounds__(TPB, 1)
rnn_persistent(const float* __restrict__ x,
               const float* __restrict__ Wx,
               const float* __restrict__ Wh,
               const float* __restrict__ bias,
               const float* __restrict__ Wfc,
               const float* __restrict__ bfc,
               float* __restrict__ out)
{
    __shared__ float sW[KTOT * 8];          // 24 KB: resident weight slice
    __shared__ float sA[MROWS * SA_STRIDE]; // 18 KB: A tile [128 x 32], padded

    const int tid = threadIdx.x;
    const int p   = blockIdx.x >> 6;   // batch half
    const int q   = blockIdx.x & 63;   // column tile
    const int q8  = q << 3;

    // Load the persistent weight slice: rows 0..511 = Wh[:, q8..q8+7],
    // rows 512..767 = Wx[:, q8..q8+7].
    for (int i = tid; i < KTOT * 8; i += TPB) {
        int kr = i >> 3, c = i & 7;
        sW[i] = (kr < Hh) ? Wh[kr * Hh + q8 + c]
                          : Wx[(kr - Hh) * Hh + q8 + c];
    }

    // Compute-thread mapping: r = row (0..127), cc = which float4 of the 8 cols.
    const int cc = tid & 1;
    const int r  = tid >> 1;
    // Load-thread mapping: rows r0, r0+32, r0+64, r0+96; c4 = float4 column.
    const int r0 = tid >> 3;
    const int c4 = tid & 7;

    const float4  bb   = ((const float4*)bias)[q * 2 + cc];
    const float4* sW4  = (const float4*)sW;
    const float2* hrow = (const float2*)&sA[r * SA_STRIDE];

    __syncthreads();

    for (int t = 0; t < Tt; ++t) {
        const int cur = t & 1;      // read buffer (t==0 reads nothing: h0 == 0)
        const int nxt = cur ^ 1;    // write buffer
        const int kt0 = (t == 0) ? 16 : 0;

        float4 acc = make_float4(0.f, 0.f, 0.f, 0.f);
        float4 ra[4];

        // Prefetch first tile into registers.
        {
            const int kt = kt0;
            if (kt < 16) {
                const float4* src = (const float4*)g_h[cur];
                #pragma unroll
                for (int i = 0; i < 4; i++) {
                    int rr = r0 + 32 * i;
                    ra[i] = __ldcg(&src[(p * MROWS + rr) * (Hh / 4) + kt * 8 + c4]);
                }
            } else {
                const float4* src = (const float4*)x;
                #pragma unroll
                for (int i = 0; i < 4; i++) {
                    int rr = r0 + 32 * i;
                    ra[i] = __ldg(&src[((p * MROWS + rr) * Tt + t) * (Ff / 4)
                                       + (kt - 16) * 8 + c4]);
                }
            }
        }

        for (int kt = kt0; kt < NTILE; ++kt) {
            // Stage current tile to smem.
            #pragma unroll
            for (int i = 0; i < 4; i++) {
                *(float4*)&sA[(r0 + 32 * i) * SA_STRIDE + c4 * 4] = ra[i];
            }
            __syncthreads();

            // Prefetch next tile (LDG latency overlaps compute below).
            if (kt + 1 < NTILE) {
                const int kn = kt + 1;
                if (kn < 16) {
                    const float4* src = (const float4*)g_h[cur];
                    #pragma unroll
                    for (int i = 0; i < 4; i++) {
                        int rr = r0 + 32 * i;
                        ra[i] = __ldcg(&src[(p * MROWS + rr) * (Hh / 4) + kn * 8 + c4]);
                    }
                } else {
                    const float4* src = (const float4*)x;
                    #pragma unroll
                    for (int i = 0; i < 4; i++) {
                        int rr = r0 + 32 * i;
                        ra[i] = __ldg(&src[((p * MROWS + rr) * Tt + t) * (Ff / 4)
                                           + (kn - 16) * 8 + c4]);
                    }
                }
            }

            // Compute: acc[0..3] += A[r, k] * W[k, cc*4..cc*4+3], k over this tile.
            {
                const int wbase = kt * 64 + cc;
                #pragma unroll
                for (int kk2 = 0; kk2 < 16; kk2++) {
                    float2 h2 = hrow[kk2];
                    float4 w0 = sW4[wbase + 4 * kk2];
                    float4 w1 = sW4[wbase + 4 * kk2 + 2];
                    acc.x = fmaf(h2.x, w0.x, acc.x);
                    acc.y = fmaf(h2.x, w0.y, acc.y);
                    acc.z = fmaf(h2.x, w0.z, acc.z);
                    acc.w = fmaf(h2.x, w0.w, acc.w);
                    acc.x = fmaf(h2.y, w1.x, acc.x);
                    acc.y = fmaf(h2.y, w1.y, acc.y);
                    acc.z = fmaf(h2.y, w1.z, acc.z);
                    acc.w = fmaf(h2.y, w1.w, acc.w);
                }
            }
            __syncthreads();
        }

        // Epilogue: bias + tanh, write next hidden state (L2-coherent store).
        float4 hn;
        hn.x = tanhf(acc.x + bb.x);
        hn.y = tanhf(acc.y + bb.y);
        hn.z = tanhf(acc.z + bb.z);
        hn.w = tanhf(acc.w + bb.w);
        __stcg(&((float4*)g_h[nxt])[(p * MROWS + r) * (Hh / 4) + q * 2 + cc], hn);

        grid_barrier(t);
    }

    // Final Dense(1): s[b] = h_last[b,:] . Wfc + bfc - LAMBDA_G*RT.
    // h_last lives in g_h[0] (512 steps -> last write was to buffer 0).
    if (blockIdx.x < 8) {
        const int brow = blockIdx.x * 32 + (tid >> 3);
        const int l    = tid & 7;
        float s = 0.f;
        const float* hr = &g_h[0][brow * Hh];
        for (int k = l; k < Hh; k += 8)
            s += __ldcg(&hr[k]) * __ldg(&Wfc[k]);
        s += __shfl_down_sync(0xffffffffu, s, 4, 8);
        s += __shfl_down_sync(0xffffffffu, s, 2, 8);
        s += __shfl_down_sync(0xffffffffu, s, 1, 8);
        if (l == 0) out[brow] = s + __ldg(bfc) - 0.05f;
    }

    // Exit barrier: last CTA resets barrier state so graph replays start clean.
    __syncthreads();
    if (tid == 0) {
        __threadfence();
        unsigned e = atomicAdd(&g_exit, 1u);
        if (e == (unsigned)(NCTA - 1)) {
            #pragma unroll
            for (int i = 0; i < 8; i++) g_cnt[i * 64] = 0u;
            g_master = 0u;
            g_gen    = 0u;
            g_exit   = 0u;
            __threadfence();
        }
    }
}

extern "C" void kernel_launch(void* const* d_in, const int* in_sizes, int n_in,
                              void* d_out, int out_size) {
    const float* x   = (const float*)d_in[0];
    const float* Wx  = (const float*)d_in[1];
    const float* Wh  = (const float*)d_in[2];
    const float* b   = (const float*)d_in[3];
    const float* Wfc = (const float*)d_in[4];
    const float* bfc = (const float*)d_in[5];
    float* out = (float*)d_out;
    (void)in_sizes; (void)n_in; (void)out_size;
    rnn_persistent<<<NCTA, TPB>>>(x, Wx, Wh, b, Wfc, bfc, out);
}

// round 3
// speedup vs baseline: 1.0052x; 1.0052x over previous
#include <cuda_runtime.h>

// Elman RNN, persistent-kernel formulation.
// grid = 128 CTAs: p = blockIdx>>6 picks batch half (128 rows), q = blockIdx&63
// picks 8 output columns. Each CTA keeps its [Wh;Wx] column slice in smem for
// the whole run. Recurrent state ping-pongs through __device__ global memory
// with .cg loads/stores (L1 is not coherent across SMs). One two-level atomic
// grid barrier per timestep.

#define NCTA 128
#define TPB  256

#define Bb 256
#define Tt 512
#define Ff 256
#define Hh 512
#define KTOT 768          // Hh + Ff (fused K: recurrent part then input part)
#define NTILE 24          // KTOT / 32
#define KTILE 32
#define MROWS 128         // batch rows per group
#define SA_STRIDE 36      // padded row stride (floats) for the A tile

__device__ float    g_h[2][Bb * Hh];   // ping-pong hidden state, zero-init by CUDA
__device__ unsigned g_cnt[8 * 64];     // 8 arrival cells, 256B apart
__device__ unsigned g_master;
__device__ unsigned g_gen;
__device__ unsigned g_exit;

__device__ __forceinline__ void grid_barrier(int bar) {
    __syncthreads();
    if (threadIdx.x == 0) {
        __threadfence();
        unsigned cell = blockIdx.x & 7u;
        unsigned prev = atomicAdd(&g_cnt[cell * 64], 1u);
        if (prev == 16u * (unsigned)(bar + 1) - 1u) {        // last in cell
            unsigned m = atomicAdd(&g_master, 1u);
            if (m == 8u * (unsigned)(bar + 1) - 1u) {        // last cell
                atomicExch(&g_gen, (unsigned)(bar + 1));     // release
            }
        }
        while (*((volatile unsigned*)&g_gen) < (unsigned)(bar + 1)) { }
        __threadfence();
    }
    __syncthreads();
}

__global__ void __launch_bounds__(TPB, 1)
rnn_persistent(const float* __restrict__ x,
               const float* __restrict__ Wx,
               const float* __restrict__ Wh,
               const float* __restrict__ bias,
               const float* __restrict__ Wfc,
               const float* __restrict__ bfc,
               float* __restrict__ out)
{
    __shared__ float sW[KTOT * 8];          // 24 KB: resident weight slice
    __shared__ float sA[MROWS * SA_STRIDE]; // 18 KB: A tile [128 x 32], padded

    const int tid = threadIdx.x;
    const int p   = blockIdx.x >> 6;   // batch half
    const int q   = blockIdx.x & 63;   // column tile
    const int q8  = q << 3;

    // Load the persistent weight slice: rows 0..511 = Wh[:, q8..q8+7],
    // rows 512..767 = Wx[:, q8..q8+7].
    for (int i = tid; i < KTOT * 8; i += TPB) {
        int kr = i >> 3, c = i & 7;
        sW[i] = (kr < Hh) ? Wh[kr * Hh + q8 + c]
                          : Wx[(kr - Hh) * Hh + q8 + c];
    }

    // Compute-thread mapping: r = row (0..127), cc = which float4 of the 8 cols.
    const int cc = tid & 1;
    const int r  = tid >> 1;
    // Load-thread mapping: rows r0, r0+32, r0+64, r0+96; c4 = float4 column.
    const int r0 = tid >> 3;
    const int c4 = tid & 7;

    const float4  bb   = ((const float4*)bias)[q * 2 + cc];
    const float4* sW4  = (const float4*)sW;
    const float2* hrow = (const float2*)&sA[r * SA_STRIDE];

    __syncthreads();

    for (int t = 0; t < Tt; ++t) {
        const int cur = t & 1;      // read buffer (t==0 reads nothing: h0 == 0)
        const int nxt = cur ^ 1;    // write buffer
        const int kt0 = (t == 0) ? 16 : 0;

        float4 acc = make_float4(0.f, 0.f, 0.f, 0.f);
        float4 ra[4];

        // Prefetch first tile into registers.
        {
            const int kt = kt0;
            if (kt < 16) {
                const float4* src = (const float4*)g_h[cur];
                #pragma unroll
                for (int i = 0; i < 4; i++) {
                    int rr = r0 + 32 * i;
                    ra[i] = __ldcg(&src[(p * MROWS + rr) * (Hh / 4) + kt * 8 + c4]);
                }
            } else {
                const float4* src = (const float4*)x;
                #pragma unroll
                for (int i = 0; i < 4; i++) {
                    int rr = r0 + 32 * i;
                    ra[i] = __ldg(&src[((p * MROWS + rr) * Tt + t) * (Ff / 4)
                                       + (kt - 16) * 8 + c4]);
                }
            }
        }

        for (int kt = kt0; kt < NTILE; ++kt) {
            // Stage current tile to smem.
            #pragma unroll
            for (int i = 0; i < 4; i++) {
                *(float4*)&sA[(r0 + 32 * i) * SA_STRIDE + c4 * 4] = ra[i];
            }
            __syncthreads();

            // Prefetch next tile (LDG latency overlaps compute below).
            if (kt + 1 < NTILE) {
                const int kn = kt + 1;
                if (kn < 16) {
                    const float4* src = (const float4*)g_h[cur];
                    #pragma unroll
                    for (int i = 0; i < 4; i++) {
                        int rr = r0 + 32 * i;
                        ra[i] = __ldcg(&src[(p * MROWS + rr) * (Hh / 4) + kn * 8 + c4]);
                    }
                } else {
                    const float4* src = (const float4*)x;
                    #pragma unroll
                    for (int i = 0; i < 4; i++) {
                        int rr = r0 + 32 * i;
                        ra[i] = __ldg(&src[((p * MROWS + rr) * Tt + t) * (Ff / 4)
                                           + (kn - 16) * 8 + c4]);
                    }
                }
            }

            // Compute: acc[0..3] += A[r, k] * W[k, cc*4..cc*4+3], k over this tile.
            {
                const int wbase = kt * 64 + cc;
                #pragma unroll
                for (int kk2 = 0; kk2 < 16; kk2++) {
                    float2 h2 = hrow[kk2];
                    float4 w0 = sW4[wbase + 4 * kk2];
                    float4 w1 = sW4[wbase + 4 * kk2 + 2];
                    acc.x = fmaf(h2.x, w0.x, acc.x);
                    acc.y = fmaf(h2.x, w0.y, acc.y);
                    acc.z = fmaf(h2.x, w0.z, acc.z);
                    acc.w = fmaf(h2.x, w0.w, acc.w);
                    acc.x = fmaf(h2.y, w1.x, acc.x);
                    acc.y = fmaf(h2.y, w1.y, acc.y);
                    acc.z = fmaf(h2.y, w1.z, acc.z);
                    acc.w = fmaf(h2.y, w1.w, acc.w);
                }
            }
            __syncthreads();
        }

        // Epilogue: bias + tanh, write next hidden state (L2-coherent store).
        float4 hn;
        hn.x = tanhf(acc.x + bb.x);
        hn.y = tanhf(acc.y + bb.y);
        hn.z = tanhf(acc.z + bb.z);
        hn.w = tanhf(acc.w + bb.w);
        __stcg(&((float4*)g_h[nxt])[(p * MROWS + r) * (Hh / 4) + q * 2 + cc], hn);

        grid_barrier(t);
    }

    // Final Dense(1): s[b] = h_last[b,:] . Wfc + bfc - LAMBDA_G*RT.
    // h_last lives in g_h[0] (512 steps -> last write was to buffer 0).
    if (blockIdx.x < 8) {
        const int brow = blockIdx.x * 32 + (tid >> 3);
        const int l    = tid & 7;
        float s = 0.f;
        const float* hr = &g_h[0][brow * Hh];
        for (int k = l; k < Hh; k += 8)
            s += __ldcg(&hr[k]) * __ldg(&Wfc[k]);
        s += __shfl_down_sync(0xffffffffu, s, 4, 8);
        s += __shfl_down_sync(0xffffffffu, s, 2, 8);
        s += __shfl_down_sync(0xffffffffu, s, 1, 8);
        if (l == 0) out[brow] = s + __ldg(bfc) - 0.05f;
    }

    // Exit barrier: last CTA resets barrier state so graph replays start clean.
    __syncthreads();
    if (tid == 0) {
        __threadfence();
        unsigned e = atomicAdd(&g_exit, 1u);
        if (e == (unsigned)(NCTA - 1)) {
            #pragma unroll
            for (int i = 0; i < 8; i++) g_cnt[i * 64] = 0u;
            g_master = 0u;
            g_gen    = 0u;
            g_exit   = 0u;
            __threadfence();
        }
    }
}

extern "C" void kernel_launch(void* const* d_in, const int* in_sizes, int n_in,
                              void* d_out, int out_size) {
    const float* x   = (const float*)d_in[0];
    const float* Wx  = (const float*)d_in[1];
    const float* Wh  = (const float*)d_in[2];
    const float* b   = (const float*)d_in[3];
    const float* Wfc = (const float*)d_in[4];
    const float* bfc = (const float*)d_in[5];
    float* out = (float*)d_out;
    (void)in_sizes; (void)n_in; (void)out_size;
    rnn_persistent<<<NCTA, TPB>>>(x, Wx, Wh, b, Wfc, bfc, out);
}

// round 5
// speedup vs baseline: 1.8235x; 1.8141x over previous
#include <cuda_runtime.h>
#include <cuda_bf16.h>
#include <cstdint>

#define Tt 512
#define Hh 512
#define Ff 256
#define Bb 256
#define NCTA 128
#define TPB  128

#define WSTR_E 776            // padded W row stride in elements (1552 B)
#define WSTR_B 1552
#define WHI_OFF 0
#define WLO_OFF (32 * WSTR_B)             // 49664
#define A_OFF   (2 * 32 * WSTR_B)         // 99328
#define SA_STR  144                        // A chunk row stride bytes (32 rows x 64 bf16 + pad)
#define CHUNKB  (32 * SA_STR)              // 4608
#define NBUF    6
#define SM_DYN  (A_OFF + NBUF * CHUNKB)    // 126976 B

__device__ __align__(1024) __nv_bfloat16 g_xhi[(size_t)Bb * Tt * Ff];
__device__ __align__(1024) __nv_bfloat16 g_xlo[(size_t)Bb * Tt * Ff];
__device__ __align__(1024) __nv_bfloat16 g_hhi[2][Bb * Hh];
__device__ __align__(1024) __nv_bfloat16 g_hlo[2][Bb * Hh];
__device__ unsigned g_cnt[8 * 64];
__device__ unsigned g_master, g_gen, g_exit;

// ---------------- helpers ----------------
__device__ __forceinline__ uint32_t smem_u32(const void* p) {
    uint32_t a;
    asm("{ .reg .u64 t; cvta.to.shared.u64 t, %1; cvt.u32.u64 %0, t; }" : "=r"(a) : "l"(p));
    return a;
}
__device__ __forceinline__ void cp_async16(uint32_t dst, const void* src) {
    asm volatile("cp.async.cg.shared.global [%0], [%1], 16;" :: "r"(dst), "l"(src) : "memory");
}
__device__ __forceinline__ void cp_commit() {
    asm volatile("cp.async.commit_group;" ::: "memory");
}
__device__ __forceinline__ void wait_groups(int k) {
    switch (k) {
        case 0: asm volatile("cp.async.wait_group 0;" ::: "memory"); break;
        case 1: asm volatile("cp.async.wait_group 1;" ::: "memory"); break;
        case 2: asm volatile("cp.async.wait_group 2;" ::: "memory"); break;
        default: asm volatile("cp.async.wait_group 3;" ::: "memory"); break;
    }
}
__device__ __forceinline__ void ldm_x4(uint32_t& r0, uint32_t& r1, uint32_t& r2, uint32_t& r3,
                                       uint32_t addr) {
    asm volatile("ldmatrix.sync.aligned.m8n8.x4.shared.b16 {%0,%1,%2,%3}, [%4];"
                 : "=r"(r0), "=r"(r1), "=r"(r2), "=r"(r3) : "r"(addr));
}
__device__ __forceinline__ void mma16816(float* d, const uint32_t* a, uint32_t b0, uint32_t b1) {
    asm volatile("mma.sync.aligned.m16n8k16.row.col.f32.bf16.bf16.f32 "
                 "{%0,%1,%2,%3}, {%4,%5,%6,%7}, {%8,%9}, {%0,%1,%2,%3};"
                 : "+f"(d[0]), "+f"(d[1]), "+f"(d[2]), "+f"(d[3])
                 : "r"(a[0]), "r"(a[1]), "r"(a[2]), "r"(a[3]), "r"(b0), "r"(b1));
}
__device__ __forceinline__ uint32_t packbf(__nv_bfloat16 a, __nv_bfloat16 b) {
    return (uint32_t)__bfloat16_as_ushort(a) | ((uint32_t)__bfloat16_as_ushort(b) << 16);
}
__device__ __forceinline__ void stcg32(void* p, uint32_t v) {
    asm volatile("st.global.cg.b32 [%0], %1;" :: "l"(p), "r"(v) : "memory");
}
__device__ __forceinline__ float tanh_acc(float x) {
    float e = __expf(2.f * x);          // inf-safe: x>>0 -> 1, x<<0 -> -1
    return 1.f - 2.f / (e + 1.f);
}

// ---------------- prep: split x into bf16 hi/lo ----------------
__global__ void xsplit(const float* __restrict__ x) {
    size_t base = ((size_t)blockIdx.x * 256 + threadIdx.x) * 8;
    float4 v0 = __ldg((const float4*)(x + base));
    float4 v1 = __ldg((const float4*)(x + base) + 1);
    float v[8] = {v0.x, v0.y, v0.z, v0.w, v1.x, v1.y, v1.z, v1.w};
    uint32_t ph[4], pl[4];
    #pragma unroll
    for (int j = 0; j < 4; j++) {
        __nv_bfloat16 h0 = __float2bfloat16(v[2*j]);
        __nv_bfloat16 h1 = __float2bfloat16(v[2*j+1]);
        __nv_bfloat16 l0 = __float2bfloat16(v[2*j]   - __bfloat162float(h0));
        __nv_bfloat16 l1 = __float2bfloat16(v[2*j+1] - __bfloat162float(h1));
        ph[j] = packbf(h0, h1); pl[j] = packbf(l0, l1);
    }
    *(uint4*)&g_xhi[base] = make_uint4(ph[0], ph[1], ph[2], ph[3]);
    *(uint4*)&g_xlo[base] = make_uint4(pl[0], pl[1], pl[2], pl[3]);
}

// ---------------- grid barrier: 8 cells x 16 arrivals ----------------
__device__ __forceinline__ void grid_barrier(int gen) {
    __syncthreads();
    if (threadIdx.x == 0) {
        __threadfence();
        unsigned cell = blockIdx.x & 7u;
        unsigned prev = atomicAdd(&g_cnt[cell * 64], 1u);
        if (prev == 16u * (unsigned)(gen + 1) - 1u) {
            unsigned m = atomicAdd(&g_master, 1u);
            if (m == 8u * (unsigned)(gen + 1) - 1u)
                atomicExch(&g_gen, (unsigned)(gen + 1));
        }
        while (*(volatile unsigned*)&g_gen < (unsigned)(gen + 1)) { }
        __threadfence();
    }
    __syncthreads();
}

// ---------------- persistent HMMA recurrence ----------------
__global__ void __launch_bounds__(TPB, 1)
rnn_mma(const float* __restrict__ Wx, const float* __restrict__ Wh,
        const float* __restrict__ bias, const float* __restrict__ Wfc,
        const float* __restrict__ bfc, float* __restrict__ out)
{
    extern __shared__ char sm[];
    const uint32_t s0 = smem_u32(sm);

    const int tid  = threadIdx.x;
    const int wid  = tid >> 5, lane = tid & 31;
    const int mq   = blockIdx.x >> 4;       // 0..7  -> rows [mq*32, +32)
    const int nq   = blockIdx.x & 15;       // 0..15 -> cols [nq*32, +32)
    const int mbase = mq * 32, qn = nq * 32;
    const int m_off = (wid >> 1) * 16;      // warp quadrant
    const int n_off = (wid & 1) * 16;

    // ---- resident split weight slice: [n 0..31][k 0..767], hi & lo ----
    __nv_bfloat16* sWhi = (__nv_bfloat16*)(sm + WHI_OFF);
    __nv_bfloat16* sWlo = (__nv_bfloat16*)(sm + WLO_OFF);
    for (int idx = tid; idx < 32 * 768; idx += TPB) {
        int n = idx / 768, k = idx - n * 768;
        float w = (k < 512) ? Wh[k * Hh + qn + n] : Wx[(k - 512) * Hh + qn + n];
        __nv_bfloat16 hi = __float2bfloat16(w);
        sWhi[n * WSTR_E + k] = hi;
        sWlo[n * WSTR_E + k] = __float2bfloat16(w - __bfloat162float(hi));
    }
    __syncthreads();

    // per-thread invariant fragment addresses
    const uint32_t aoff = (uint32_t)(m_off + (lane & 15)) * SA_STR + ((lane >> 4) << 4);
    const uint32_t boff = (uint32_t)(n_off + ((lane >> 4) << 3) + (lane & 7)) * WSTR_B
                        + (((lane >> 3) & 1) << 4);
    const uint32_t aBase = s0 + A_OFF + aoff;
    const uint32_t bHi   = s0 + WHI_OFF + boff;
    const uint32_t bLo   = s0 + WLO_OFF + boff;

    // producer mapping: thread t -> local row t>>2, 32B (2 x 16B) at seg (t&3)*2
    const int prow = tid >> 2;
    const int pseg = (tid & 3) * 2;
    const uint32_t pdst = s0 + A_OFF + (uint32_t)prow * SA_STR + (uint32_t)pseg * 16;

    // epilogue biases
    const int c0 = qn + n_off + (lane & 3) * 2;
    const float bb0 = bias[c0],     bb1 = bias[c0 + 1];
    const float bb8 = bias[c0 + 8], bb9 = bias[c0 + 9];
    const int erow0 = mbase + m_off + (lane >> 2);

    for (int t = 0; t < Tt; ++t) {
        const int cur = t & 1, nxt = cur ^ 1;
        const int NC = t ? 24 : 8;

        float D0[4] = {0.f, 0.f, 0.f, 0.f};
        float D1[4] = {0.f, 0.f, 0.f, 0.f};

        // chunk c: 0-7 h_hi, 8-11 x_hi, 12-19 h_lo, 20-23 x_lo
        // (t==0: list index i -> c skips h chunks)
        #define MAPC(i) (t ? (i) : ((i) < 4 ? (i) + 8 : (i) + 16))
        #define ISSUE(c, buf) do {                                                      \
            int _c = (c);                                                               \
            const __nv_bfloat16* _s;                                                    \
            if      (_c < 8)  _s = g_hhi[cur] + (size_t)(mbase + prow) * Hh + _c * 64;  \
            else if (_c < 12) _s = g_xhi + ((size_t)(mbase + prow) * Tt + t) * Ff + (_c - 8) * 64;  \
            else if (_c < 20) _s = g_hlo[cur] + (size_t)(mbase + prow) * Hh + (_c - 12) * 64;       \
            else              _s = g_xlo + ((size_t)(mbase + prow) * Tt + t) * Ff + (_c - 20) * 64; \
            uint32_t _d = pdst + (uint32_t)(buf) * CHUNKB;                              \
            cp_async16(_d,      (const char*)_s + pseg * 16);                           \
            cp_async16(_d + 16, (const char*)_s + pseg * 16 + 16);                      \
            cp_commit();                                                                \
        } while (0)

        {
            int npre = NC < 4 ? NC : 4;
            for (int i = 0; i < npre; i++) ISSUE(MAPC(i), i % NBUF);
        }

        for (int i = 0; i < NC; i++) {
            int ih = (i + 3 < NC - 1) ? (i + 3) : (NC - 1);
            wait_groups(ih - i);
            __syncthreads();
            if (i + 4 < NC) ISSUE(MAPC(i + 4), (i + 4) % NBUF);

            const int c  = MAPC(i);
            const int hi = (c < 12);
            const uint32_t kg2 = (uint32_t)(hi ? c : c - 12) * 128;   // kg * 2 bytes
            const uint32_t ab = aBase + (uint32_t)(i % NBUF) * CHUNKB;

            #pragma unroll
            for (int k16 = 0; k16 < 4; k16++) {
                uint32_t a[4], b0, b1, b2, b3;
                ldm_x4(a[0], a[1], a[2], a[3], ab + k16 * 32);
                ldm_x4(b0, b1, b2, b3, bHi + kg2 + k16 * 32);
                mma16816(D0, a, b0, b1);
                mma16816(D1, a, b2, b3);
                if (hi) {
                    ldm_x4(b0, b1, b2, b3, bLo + kg2 + k16 * 32);
                    mma16816(D0, a, b0, b1);
                    mma16816(D1, a, b2, b3);
                }
            }
        }
        #undef ISSUE
        #undef MAPC

        // ---- epilogue: bias + tanh + hi/lo split, store next h ----
        {
            float h00 = tanh_acc(D0[0] + bb0), h01 = tanh_acc(D0[1] + bb1);
            float h10 = tanh_acc(D0[2] + bb0), h11 = tanh_acc(D0[3] + bb1);
            float g00 = tanh_acc(D1[0] + bb8), g01 = tanh_acc(D1[1] + bb9);
            float g10 = tanh_acc(D1[2] + bb8), g11 = tanh_acc(D1[3] + bb9);
            __nv_bfloat16* dhi = g_hhi[nxt];
            __nv_bfloat16* dlo = g_hlo[nxt];
            size_t o0 = (size_t)erow0 * Hh + c0;
            size_t o1 = (size_t)(erow0 + 8) * Hh + c0;
            #define EMIT(off, va, vb) do {                                              \
                __nv_bfloat16 _a = __float2bfloat16(va), _b = __float2bfloat16(vb);     \
                stcg32(dhi + (off), packbf(_a, _b));                                    \
                stcg32(dlo + (off), packbf(__float2bfloat16((va) - __bfloat162float(_a)), \
                                           __float2bfloat16((vb) - __bfloat162float(_b)))); \
            } while (0)
            EMIT(o0,     h00, h01);
            EMIT(o1,     h10, h11);
            EMIT(o0 + 8, g00, g01);
            EMIT(o1 + 8, g10, g11);
            #undef EMIT
        }

        grid_barrier(t);
    }

    // ---- final Dense(1): h_last = buffers[0] ----
    if (blockIdx.x < 16) {
        const int brow = blockIdx.x * 16 + (tid >> 3);
        const int l = tid & 7;
        float s = 0.f;
        const __nv_bfloat16* hh = g_hhi[0] + (size_t)brow * Hh;
        const __nv_bfloat16* hl = g_hlo[0] + (size_t)brow * Hh;
        for (int k = l; k < Hh; k += 8) {
            float hv = __bfloat162float(__ldcg(&hh[k])) + __bfloat162float(__ldcg(&hl[k]));
            s += hv * __ldg(&Wfc[k]);
        }
        s += __shfl_down_sync(0xffffffffu, s, 4, 8);
        s += __shfl_down_sync(0xffffffffu, s, 2, 8);
        s += __shfl_down_sync(0xffffffffu, s, 1, 8);
        if (l == 0) out[brow] = s + __ldg(bfc) - 0.05f;
    }

    // ---- exit: last CTA resets barrier state for graph replay ----
    __syncthreads();
    if (tid == 0) {
        __threadfence();
        unsigned e = atomicAdd(&g_exit, 1u);
        if (e == (unsigned)(NCTA - 1)) {
            #pragma unroll
            for (int i = 0; i < 8; i++) g_cnt[i * 64] = 0u;
            g_master = 0u; g_gen = 0u; g_exit = 0u;
            __threadfence();
        }
    }
}

extern "C" void kernel_launch(void* const* d_in, const int* in_sizes, int n_in,
                              void* d_out, int out_size) {
    const float* x   = (const float*)d_in[0];
    const float* Wx  = (const float*)d_in[1];
    const float* Wh  = (const float*)d_in[2];
    const float* b   = (const float*)d_in[3];
    const float* Wfc = (const float*)d_in[4];
    const float* bfc = (const float*)d_in[5];
    float* out = (float*)d_out;
    (void)in_sizes; (void)n_in; (void)out_size;

    cudaFuncSetAttribute(rnn_mma, cudaFuncAttributeMaxDynamicSharedMemorySize, SM_DYN);
    xsplit<<<16384, 256>>>(x);
    rnn_mma<<<NCTA, TPB, SM_DYN>>>(Wx, Wh, b, Wfc, bfc, out);
}

// round 6
// speedup vs baseline: 2.0408x; 1.1191x over previous
#include <cuda_runtime.h>
#include <cuda_bf16.h>
#include <cstdint>

#define Tt 512
#define Hh 512
#define Ff 256
#define Bb 256
#define NCTA 128
#define TPB  256

#define WSTR_E 776             // padded W row stride (elements); 1552 B
#define WSTR_B 1552
#define WHI_OFF 0
#define WLO_OFF (32 * WSTR_B)
#define A_OFF   (2 * 32 * WSTR_B)          // 99328
#define SA_STR  144                         // A row stride bytes (128B data + 16B pad)
#define CHUNKB  (32 * SA_STR)               // 4608
#define SLOTS   4                           // pair slots in ring
#define A_BYTES (SLOTS * 2 * CHUNKB)        // 36864
#define RED_OFF (A_OFF + A_BYTES)
#define SM_DYN  (RED_OFF + 4096)            // 140288 B

__device__ __align__(1024) __nv_bfloat16 g_xhi[(size_t)Bb * Tt * Ff];
__device__ __align__(1024) __nv_bfloat16 g_xlo[(size_t)Bb * Tt * Ff];
__device__ __align__(1024) __nv_bfloat16 g_hhi[2][Bb * Hh];
__device__ __align__(1024) __nv_bfloat16 g_hlo[2][Bb * Hh];
__device__ unsigned g_cnt[8 * 64];
__device__ unsigned g_master, g_gen, g_exit;

// ---------------- helpers ----------------
__device__ __forceinline__ uint32_t smem_u32(const void* p) {
    uint32_t a;
    asm("{ .reg .u64 t; cvta.to.shared.u64 t, %1; cvt.u32.u64 %0, t; }" : "=r"(a) : "l"(p));
    return a;
}
__device__ __forceinline__ void cp_async16(uint32_t dst, const void* src) {
    asm volatile("cp.async.cg.shared.global [%0], [%1], 16;" :: "r"(dst), "l"(src) : "memory");
}
__device__ __forceinline__ void cp_commit() {
    asm volatile("cp.async.commit_group;" ::: "memory");
}
__device__ __forceinline__ void wait_groups(int k) {
    switch (k) {
        case 0: asm volatile("cp.async.wait_group 0;" ::: "memory"); break;
        case 1: asm volatile("cp.async.wait_group 1;" ::: "memory"); break;
        default: asm volatile("cp.async.wait_group 2;" ::: "memory"); break;
    }
}
__device__ __forceinline__ void ldm_x4(uint32_t& r0, uint32_t& r1, uint32_t& r2, uint32_t& r3,
                                       uint32_t addr) {
    asm volatile("ldmatrix.sync.aligned.m8n8.x4.shared.b16 {%0,%1,%2,%3}, [%4];"
                 : "=r"(r0), "=r"(r1), "=r"(r2), "=r"(r3) : "r"(addr));
}
__device__ __forceinline__ void mma16816(float* d, const uint32_t* a, uint32_t b0, uint32_t b1) {
    asm volatile("mma.sync.aligned.m16n8k16.row.col.f32.bf16.bf16.f32 "
                 "{%0,%1,%2,%3}, {%4,%5,%6,%7}, {%8,%9}, {%0,%1,%2,%3};"
                 : "+f"(d[0]), "+f"(d[1]), "+f"(d[2]), "+f"(d[3])
                 : "r"(a[0]), "r"(a[1]), "r"(a[2]), "r"(a[3]), "r"(b0), "r"(b1));
}
__device__ __forceinline__ uint32_t packbf(__nv_bfloat16 a, __nv_bfloat16 b) {
    return (uint32_t)__bfloat16_as_ushort(a) | ((uint32_t)__bfloat16_as_ushort(b) << 16);
}
__device__ __forceinline__ void stcg32(void* p, uint32_t v) {
    asm volatile("st.global.cg.b32 [%0], %1;" :: "l"(p), "r"(v) : "memory");
}
__device__ __forceinline__ float tanh_acc(float x) {
    float e = __expf(2.f * x);
    return 1.f - 2.f / (e + 1.f);
}
// chunk order: x pairs first (prefetchable pre-barrier), then h pairs.
// i<4 -> x_hi(8..11); i<8 -> x_lo(20..23); i<16 -> h_hi(0..7); else h_lo(12..19)
__device__ __forceinline__ int mapc(int i) {
    return (i < 4) ? i + 8 : (i < 8) ? i + 16 : (i < 16) ? i - 8 : i - 4;
}

// ---------------- prep: split x into bf16 hi/lo ----------------
__global__ void xsplit(const float* __restrict__ x) {
    size_t base = ((size_t)blockIdx.x * 256 + threadIdx.x) * 8;
    float4 v0 = __ldg((const float4*)(x + base));
    float4 v1 = __ldg((const float4*)(x + base) + 1);
    float v[8] = {v0.x, v0.y, v0.z, v0.w, v1.x, v1.y, v1.z, v1.w};
    uint32_t ph[4], pl[4];
    #pragma unroll
    for (int j = 0; j < 4; j++) {
        __nv_bfloat16 h0 = __float2bfloat16(v[2*j]);
        __nv_bfloat16 h1 = __float2bfloat16(v[2*j+1]);
        __nv_bfloat16 l0 = __float2bfloat16(v[2*j]   - __bfloat162float(h0));
        __nv_bfloat16 l1 = __float2bfloat16(v[2*j+1] - __bfloat162float(h1));
        ph[j] = packbf(h0, h1); pl[j] = packbf(l0, l1);
    }
    *(uint4*)&g_xhi[base] = make_uint4(ph[0], ph[1], ph[2], ph[3]);
    *(uint4*)&g_xlo[base] = make_uint4(pl[0], pl[1], pl[2], pl[3]);
}

// ---------------- grid barrier: 8 cells x 16 arrivals ----------------
__device__ __forceinline__ void grid_barrier(int gen) {
    __syncthreads();
    if (threadIdx.x == 0) {
        __threadfence();
        unsigned cell = blockIdx.x & 7u;
        unsigned prev = atomicAdd(&g_cnt[cell * 64], 1u);
        if (prev == 16u * (unsigned)(gen + 1) - 1u) {
            unsigned m = atomicAdd(&g_master, 1u);
            if (m == 8u * (unsigned)(gen + 1) - 1u)
                atomicExch(&g_gen, (unsigned)(gen + 1));
        }
        while (*(volatile unsigned*)&g_gen < (unsigned)(gen + 1)) { }
        __threadfence();
    }
    __syncthreads();
}

// ---------------- persistent HMMA recurrence, 8 warps ----------------
__global__ void __launch_bounds__(TPB, 1)
rnn_mma(const float* __restrict__ Wx, const float* __restrict__ Wh,
        const float* __restrict__ bias, const float* __restrict__ Wfc,
        const float* __restrict__ bfc, float* __restrict__ out)
{
    extern __shared__ char sm[];
    const uint32_t s0 = smem_u32(sm);

    const int tid  = threadIdx.x;
    const int wid  = tid >> 5, lane = tid & 31;
    const int grp  = wid >> 2;              // chunk-parity group
    const int qw   = wid & 3;               // quadrant within 32x32 tile
    const int mq   = blockIdx.x >> 4;
    const int nq   = blockIdx.x & 15;
    const int mbase = mq * 32, qn = nq * 32;
    const int m_off = (qw >> 1) * 16;
    const int n_off = (qw & 1) * 16;

    // ---- resident split weight slice ----
    __nv_bfloat16* sWhi = (__nv_bfloat16*)(sm + WHI_OFF);
    __nv_bfloat16* sWlo = (__nv_bfloat16*)(sm + WLO_OFF);
    for (int idx = tid; idx < 32 * 768; idx += TPB) {
        int n = idx / 768, k = idx - n * 768;
        float w = (k < 512) ? Wh[k * Hh + qn + n] : Wx[(k - 512) * Hh + qn + n];
        __nv_bfloat16 hi = __float2bfloat16(w);
        sWhi[n * WSTR_E + k] = hi;
        sWlo[n * WSTR_E + k] = __float2bfloat16(w - __bfloat162float(hi));
    }
    __syncthreads();

    // fragment addresses (invariant)
    const uint32_t aoff = (uint32_t)(m_off + (lane & 15)) * SA_STR + ((lane >> 4) << 4);
    const uint32_t boff = (uint32_t)(n_off + ((lane >> 4) << 3) + (lane & 7)) * WSTR_B
                        + (((lane >> 3) & 1) << 4);
    const uint32_t aBase = s0 + A_OFF + aoff;
    const uint32_t bHi   = s0 + WHI_OFF + boff;
    const uint32_t bLo   = s0 + WLO_OFF + boff;

    // producer mapping: 256 threads cover one pair (2 chunks x 32 rows x 128B);
    // thread -> chunk tid>>7, row (tid>>2)&31, 32B segment tid&3.
    const int pcid = tid >> 7;
    const int prow = (tid >> 2) & 31;
    const int pseg = tid & 3;
    const uint32_t pdst0 = s0 + A_OFF + (uint32_t)pcid * CHUNKB
                         + (uint32_t)prow * SA_STR + (uint32_t)pseg * 32;

    float* red = (float*)(sm + RED_OFF);

    // epilogue constants (warps 0-3 only)
    const int c0 = qn + n_off + (lane & 3) * 2;
    const float bb0 = bias[c0],     bb1 = bias[c0 + 1];
    const float bb8 = bias[c0 + 8], bb9 = bias[c0 + 9];
    const int erow0 = mbase + m_off + (lane >> 2);

    // issue one pair q of step s into ring slot q&3
    #define ISSUE_PAIR(s, q) do {                                                        \
        int _i = (q) * 2 + pcid;                                                         \
        int _c = mapc(_i);                                                               \
        const __nv_bfloat16* _src;                                                       \
        if      (_c < 8)  _src = g_hhi[(s) & 1] + (size_t)(mbase + prow) * Hh + _c * 64; \
        else if (_c < 12) _src = g_xhi + ((size_t)(mbase + prow) * Tt + (s)) * Ff + (_c - 8) * 64;   \
        else if (_c < 20) _src = g_hlo[(s) & 1] + (size_t)(mbase + prow) * Hh + (_c - 12) * 64;      \
        else              _src = g_xlo + ((size_t)(mbase + prow) * Tt + (s)) * Ff + (_c - 20) * 64;  \
        uint32_t _d = pdst0 + (uint32_t)((q) & 3) * (2 * CHUNKB);                        \
        _src += pseg * 16;                                                               \
        cp_async16(_d,      _src);                                                       \
        cp_async16(_d + 16, (const char*)_src + 16);                                     \
        cp_commit();                                                                     \
    } while (0)

    // initial prefetch for t=0: pairs 0..2 (x data)
    ISSUE_PAIR(0, 0); ISSUE_PAIR(0, 1); ISSUE_PAIR(0, 2);

    for (int t = 0; t < Tt; ++t) {
        const int NP = t ? 12 : 4;
        int issued = 3;

        float D0a[4] = {0,0,0,0}, D0b[4] = {0,0,0,0};
        float D1a[4] = {0,0,0,0}, D1b[4] = {0,0,0,0};

        for (int p = 0; p < NP; ++p) {
            int k = issued - p - 1; if (k > 2) k = 2;
            wait_groups(k);
            __syncthreads();
            if (issued < NP) { ISSUE_PAIR(t, issued); issued++; }

            // my group's chunk of this pair
            const int i = 2 * p + grp;
            const int c = mapc(i);
            const int hi = (c < 12);
            const uint32_t kg2 = (uint32_t)(hi ? c : c - 12) * 128;
            const uint32_t ab = aBase + (uint32_t)((p & 3) * 2 + grp) * CHUNKB;

            #pragma unroll
            for (int k16 = 0; k16 < 4; k16++) {
                float* P0 = (k16 & 1) ? D0b : D0a;
                float* P1 = (k16 & 1) ? D1b : D1a;
                uint32_t a[4], b0, b1, b2, b3;
                ldm_x4(a[0], a[1], a[2], a[3], ab + k16 * 32);
                ldm_x4(b0, b1, b2, b3, bHi + kg2 + k16 * 32);
                mma16816(P0, a, b0, b1);
                mma16816(P1, a, b2, b3);
                if (hi) {
                    ldm_x4(b0, b1, b2, b3, bLo + kg2 + k16 * 32);
                    mma16816(P0, a, b0, b1);
                    mma16816(P1, a, b2, b3);
                }
            }
        }

        // prefetch next step's x pairs before barrier (x is step-independent data)
        if (t + 1 < Tt) { ISSUE_PAIR(t + 1, 0); ISSUE_PAIR(t + 1, 1); ISSUE_PAIR(t + 1, 2); }

        // ---- cross-group reduction ----
        if (grp == 1) {
            float* rp = red + ((qw * 32 + lane) << 3);
            rp[0] = D0a[0] + D0b[0]; rp[1] = D0a[1] + D0b[1];
            rp[2] = D0a[2] + D0b[2]; rp[3] = D0a[3] + D0b[3];
            rp[4] = D1a[0] + D1b[0]; rp[5] = D1a[1] + D1b[1];
            rp[6] = D1a[2] + D1b[2]; rp[7] = D1a[3] + D1b[3];
        }
        __syncthreads();

        if (grp == 0) {
            const float* rp = red + ((qw * 32 + lane) << 3);
            float v00 = D0a[0] + D0b[0] + rp[0], v01 = D0a[1] + D0b[1] + rp[1];
            float v02 = D0a[2] + D0b[2] + rp[2], v03 = D0a[3] + D0b[3] + rp[3];
            float v10 = D1a[0] + D1b[0] + rp[4], v11 = D1a[1] + D1b[1] + rp[5];
            float v12 = D1a[2] + D1b[2] + rp[6], v13 = D1a[3] + D1b[3] + rp[7];

            float h00 = tanh_acc(v00 + bb0), h01 = tanh_acc(v01 + bb1);
            float h10 = tanh_acc(v02 + bb0), h11 = tanh_acc(v03 + bb1);
            float g00 = tanh_acc(v10 + bb8), g01 = tanh_acc(v11 + bb9);
            float g10 = tanh_acc(v12 + bb8), g11 = tanh_acc(v13 + bb9);

            const int nxt = (t & 1) ^ 1;
            __nv_bfloat16* dhi = g_hhi[nxt];
            __nv_bfloat16* dlo = g_hlo[nxt];
            size_t o0 = (size_t)erow0 * Hh + c0;
            size_t o1 = (size_t)(erow0 + 8) * Hh + c0;
            #define EMIT(off, va, vb) do {                                              \
                __nv_bfloat16 _a = __float2bfloat16(va), _b = __float2bfloat16(vb);     \
                stcg32(dhi + (off), packbf(_a, _b));                                    \
                stcg32(dlo + (off), packbf(__float2bfloat16((va) - __bfloat162float(_a)), \
                                           __float2bfloat16((vb) - __bfloat162float(_b)))); \
            } while (0)
            EMIT(o0,     h00, h01);
            EMIT(o1,     h10, h11);
            EMIT(o0 + 8, g00, g01);
            EMIT(o1 + 8, g10, g11);
            #undef EMIT
        }

        grid_barrier(t);
    }
    #undef ISSUE_PAIR

    // ---- final Dense(1): h_last = buffers[0] ----
    if (blockIdx.x < 16 && tid < 128) {
        const int brow = blockIdx.x * 16 + (tid >> 3);
        const int l = tid & 7;
        float s = 0.f;
        const __nv_bfloat16* hh = g_hhi[0] + (size_t)brow * Hh;
        const __nv_bfloat16* hl = g_hlo[0] + (size_t)brow * Hh;
        for (int k = l; k < Hh; k += 8) {
            float hv = __bfloat162float(__ldcg(&hh[k])) + __bfloat162float(__ldcg(&hl[k]));
            s += hv * __ldg(&Wfc[k]);
        }
        s += __shfl_down_sync(0xffffffffu, s, 4, 8);
        s += __shfl_down_sync(0xffffffffu, s, 2, 8);
        s += __shfl_down_sync(0xffffffffu, s, 1, 8);
        if (l == 0) out[brow] = s + __ldg(bfc) - 0.05f;
    }

    // ---- exit: last CTA resets barrier state for graph replay ----
    __syncthreads();
    if (tid == 0) {
        __threadfence();
        unsigned e = atomicAdd(&g_exit, 1u);
        if (e == (unsigned)(NCTA - 1)) {
            #pragma unroll
            for (int i = 0; i < 8; i++) g_cnt[i * 64] = 0u;
            g_master = 0u; g_gen = 0u; g_exit = 0u;
            __threadfence();
        }
    }
}

extern "C" void kernel_launch(void* const* d_in, const int* in_sizes, int n_in,
                              void* d_out, int out_size) {
    const float* x   = (const float*)d_in[0];
    const float* Wx  = (const float*)d_in[1];
    const float* Wh  = (const float*)d_in[2];
    const float* b   = (const float*)d_in[3];
    const float* Wfc = (const float*)d_in[4];
    const float* bfc = (const float*)d_in[5];
    float* out = (float*)d_out;
    (void)in_sizes; (void)n_in; (void)out_size;

    cudaFuncSetAttribute(rnn_mma, cudaFuncAttributeMaxDynamicSharedMemorySize, SM_DYN);
    xsplit<<<16384, 256>>>(x);
    rnn_mma<<<NCTA, TPB, SM_DYN>>>(Wx, Wh, b, Wfc, bfc, out);
}

// round 7
// speedup vs baseline: 2.8903x; 1.4163x over previous
#include <cuda_runtime.h>
#include <cuda_bf16.h>
#include <cstdint>

#define Tt 512
#define Hh 512
#define Ff 256
#define Bb 256
#define NCTA 128
#define TPB  256

#define WSTR_E 776             // padded W row stride (elements); 1552 B
#define WSTR_B 1552
#define WHI_OFF 0
#define WLO_OFF (32 * WSTR_B)
#define A_OFF   (2 * 32 * WSTR_B)          // 99328
#define SA_STR  144                         // A row stride bytes (128B data + 16B pad)
#define CHUNKB  (32 * SA_STR)               // 4608
#define A_BYTES (24 * CHUNKB)               // 110592: whole step resident
#define RED_OFF (A_OFF + A_BYTES)           // 209920
#define SM_DYN  (RED_OFF + 4096)            // 214016 B

__device__ __align__(1024) __nv_bfloat16 g_xhi[(size_t)Bb * Tt * Ff];
__device__ __align__(1024) __nv_bfloat16 g_xlo[(size_t)Bb * Tt * Ff];
__device__ __align__(1024) __nv_bfloat16 g_hhi[2][Bb * Hh];
__device__ __align__(1024) __nv_bfloat16 g_hlo[2][Bb * Hh];
__device__ unsigned g_cnt[8 * 64];
__device__ unsigned g_master, g_gen, g_exit;

// ---------------- helpers ----------------
__device__ __forceinline__ uint32_t smem_u32(const void* p) {
    uint32_t a;
    asm("{ .reg .u64 t; cvta.to.shared.u64 t, %1; cvt.u32.u64 %0, t; }" : "=r"(a) : "l"(p));
    return a;
}
__device__ __forceinline__ void cp_async16(uint32_t dst, const void* src) {
    asm volatile("cp.async.cg.shared.global [%0], [%1], 16;" :: "r"(dst), "l"(src) : "memory");
}
__device__ __forceinline__ void cp_commit() {
    asm volatile("cp.async.commit_group;" ::: "memory");
}
__device__ __forceinline__ void wait_groups(int k) {
    switch (k) {
        case 0: asm volatile("cp.async.wait_group 0;" ::: "memory"); break;
        case 1: asm volatile("cp.async.wait_group 1;" ::: "memory"); break;
        case 2: asm volatile("cp.async.wait_group 2;" ::: "memory"); break;
        case 3: asm volatile("cp.async.wait_group 3;" ::: "memory"); break;
        default: asm volatile("cp.async.wait_group 4;" ::: "memory"); break;
    }
}
__device__ __forceinline__ void ldm_x4(uint32_t& r0, uint32_t& r1, uint32_t& r2, uint32_t& r3,
                                       uint32_t addr) {
    asm volatile("ldmatrix.sync.aligned.m8n8.x4.shared.b16 {%0,%1,%2,%3}, [%4];"
                 : "=r"(r0), "=r"(r1), "=r"(r2), "=r"(r3) : "r"(addr));
}
__device__ __forceinline__ void mma16816(float* d, const uint32_t* a, uint32_t b0, uint32_t b1) {
    asm volatile("mma.sync.aligned.m16n8k16.row.col.f32.bf16.bf16.f32 "
                 "{%0,%1,%2,%3}, {%4,%5,%6,%7}, {%8,%9}, {%0,%1,%2,%3};"
                 : "+f"(d[0]), "+f"(d[1]), "+f"(d[2]), "+f"(d[3])
                 : "r"(a[0]), "r"(a[1]), "r"(a[2]), "r"(a[3]), "r"(b0), "r"(b1));
}
__device__ __forceinline__ uint32_t packbf(__nv_bfloat16 a, __nv_bfloat16 b) {
    return (uint32_t)__bfloat16_as_ushort(a) | ((uint32_t)__bfloat16_as_ushort(b) << 16);
}
__device__ __forceinline__ void stcg32(void* p, uint32_t v) {
    asm volatile("st.global.cg.b32 [%0], %1;" :: "l"(p), "r"(v) : "memory");
}
__device__ __forceinline__ float tanh_acc(float x) {
    float e = __expf(2.f * x);
    return 1.f - 2.f / (e + 1.f);
}

// ---------------- prep: split x into bf16 hi/lo ----------------
__global__ void xsplit(const float* __restrict__ x) {
    size_t base = ((size_t)blockIdx.x * 256 + threadIdx.x) * 8;
    float4 v0 = __ldg((const float4*)(x + base));
    float4 v1 = __ldg((const float4*)(x + base) + 1);
    float v[8] = {v0.x, v0.y, v0.z, v0.w, v1.x, v1.y, v1.z, v1.w};
    uint32_t ph[4], pl[4];
    #pragma unroll
    for (int j = 0; j < 4; j++) {
        __nv_bfloat16 h0 = __float2bfloat16(v[2*j]);
        __nv_bfloat16 h1 = __float2bfloat16(v[2*j+1]);
        __nv_bfloat16 l0 = __float2bfloat16(v[2*j]   - __bfloat162float(h0));
        __nv_bfloat16 l1 = __float2bfloat16(v[2*j+1] - __bfloat162float(h1));
        ph[j] = packbf(h0, h1); pl[j] = packbf(l0, l1);
    }
    *(uint4*)&g_xhi[base] = make_uint4(ph[0], ph[1], ph[2], ph[3]);
    *(uint4*)&g_xlo[base] = make_uint4(pl[0], pl[1], pl[2], pl[3]);
}

// ---------------- grid barrier: 8 cells x 16 arrivals ----------------
__device__ __forceinline__ void grid_barrier(int gen) {
    __syncthreads();
    if (threadIdx.x == 0) {
        __threadfence();
        unsigned cell = blockIdx.x & 7u;
        unsigned prev = atomicAdd(&g_cnt[cell * 64], 1u);
        if (prev == 16u * (unsigned)(gen + 1) - 1u) {
            unsigned m = atomicAdd(&g_master, 1u);
            if (m == 8u * (unsigned)(gen + 1) - 1u)
                atomicExch(&g_gen, (unsigned)(gen + 1));
        }
        while (*(volatile unsigned*)&g_gen < (unsigned)(gen + 1)) { }
        __threadfence();
    }
    __syncthreads();
}

// chunk ids: 0-7 h_hi, 8-11 x_hi, 12-19 h_lo, 20-23 x_lo
__device__ __forceinline__ void compute_chunk(bool hi, int c, uint32_t aBase,
                                              uint32_t bHi, uint32_t bLo,
                                              float* D0a, float* D0b,
                                              float* D1a, float* D1b) {
    const uint32_t kg2 = (uint32_t)(hi ? c : c - 12) * 128;
    const uint32_t ab = aBase + (uint32_t)c * CHUNKB;
    #pragma unroll
    for (int k16 = 0; k16 < 4; k16++) {
        float* P0 = (k16 & 1) ? D0b : D0a;
        float* P1 = (k16 & 1) ? D1b : D1a;
        uint32_t a[4], b0, b1, b2, b3;
        ldm_x4(a[0], a[1], a[2], a[3], ab + k16 * 32);
        ldm_x4(b0, b1, b2, b3, bHi + kg2 + k16 * 32);
        mma16816(P0, a, b0, b1);
        mma16816(P1, a, b2, b3);
        if (hi) {
            ldm_x4(b0, b1, b2, b3, bLo + kg2 + k16 * 32);
            mma16816(P0, a, b0, b1);
            mma16816(P1, a, b2, b3);
        }
    }
}

// ---------------- persistent HMMA recurrence, 8 warps, flat step ----------------
__global__ void __launch_bounds__(TPB, 1)
rnn_mma(const float* __restrict__ Wx, const float* __restrict__ Wh,
        const float* __restrict__ bias, const float* __restrict__ Wfc,
        const float* __restrict__ bfc, float* __restrict__ out)
{
    extern __shared__ char sm[];
    const uint32_t s0 = smem_u32(sm);

    const int tid  = threadIdx.x;
    const int wid  = tid >> 5, lane = tid & 31;
    const int grp  = wid >> 2;              // chunk-parity group
    const int qw   = wid & 3;               // quadrant within 32x32 tile
    const int mq   = blockIdx.x >> 4;
    const int nq   = blockIdx.x & 15;
    const int mbase = mq * 32, qn = nq * 32;
    const int m_off = (qw >> 1) * 16;
    const int n_off = (qw & 1) * 16;

    // ---- resident split weight slice ----
    __nv_bfloat16* sWhi = (__nv_bfloat16*)(sm + WHI_OFF);
    __nv_bfloat16* sWlo = (__nv_bfloat16*)(sm + WLO_OFF);
    for (int idx = tid; idx < 32 * 768; idx += TPB) {
        int n = idx / 768, k = idx - n * 768;
        float w = (k < 512) ? Wh[k * Hh + qn + n] : Wx[(k - 512) * Hh + qn + n];
        __nv_bfloat16 hi = __float2bfloat16(w);
        sWhi[n * WSTR_E + k] = hi;
        sWlo[n * WSTR_E + k] = __float2bfloat16(w - __bfloat162float(hi));
    }
    __syncthreads();

    // fragment addresses (invariant)
    const uint32_t aoff = (uint32_t)(m_off + (lane & 15)) * SA_STR + ((lane >> 4) << 4);
    const uint32_t boff = (uint32_t)(n_off + ((lane >> 4) << 3) + (lane & 7)) * WSTR_B
                        + (((lane >> 3) & 1) << 4);
    const uint32_t aBase = s0 + A_OFF + aoff;
    const uint32_t bHi   = s0 + WHI_OFF + boff;
    const uint32_t bLo   = s0 + WLO_OFF + boff;

    // producer mapping: per chunk, thread -> row tid>>3, 16B segment tid&7
    const int irow = tid >> 3;
    const int iseg = tid & 7;
    const uint32_t pdst0 = s0 + A_OFF + (uint32_t)irow * SA_STR + (uint32_t)iseg * 16;

    float* red = (float*)(sm + RED_OFF);

    // epilogue constants
    const int c0 = qn + n_off + (lane & 3) * 2;
    const float bb0 = bias[c0],     bb1 = bias[c0 + 1];
    const float bb8 = bias[c0 + 8], bb9 = bias[c0 + 9];
    const int erow0 = mbase + m_off + (lane >> 2);

    #define ISSUE(s, c) do {                                                                  \
        int _c = (c);                                                                         \
        const __nv_bfloat16* _src;                                                            \
        if      (_c < 8)  _src = g_hhi[(s) & 1] + (size_t)(mbase + irow) * Hh + _c * 64;      \
        else if (_c < 12) _src = g_xhi + ((size_t)(mbase + irow) * Tt + (s)) * Ff + (_c - 8) * 64;   \
        else if (_c < 20) _src = g_hlo[(s) & 1] + (size_t)(mbase + irow) * Hh + (_c - 12) * 64;      \
        else              _src = g_xlo + ((size_t)(mbase + irow) * Tt + (s)) * Ff + (_c - 20) * 64;  \
        cp_async16(pdst0 + (uint32_t)_c * CHUNKB, (const char*)_src + iseg * 16);             \
    } while (0)

    #define ISSUE_X(s) do {                                                                   \
        ISSUE(s, 8); ISSUE(s, 9); ISSUE(s, 10); ISSUE(s, 11);                                 \
        ISSUE(s, 20); ISSUE(s, 21); ISSUE(s, 22); ISSUE(s, 23);                               \
        cp_commit();                                                                          \
    } while (0)

    // prefetch x(0)
    ISSUE_X(0);

    for (int t = 0; t < Tt; ++t) {
        const bool XI = (t + 1 < Tt);
        float D0a[4] = {0,0,0,0}, D0b[4] = {0,0,0,0};
        float D1a[4] = {0,0,0,0}, D1b[4] = {0,0,0,0};

        if (t) {
            // issue all h chunks: 4 commit groups of {h_hi pair, h_lo pair}
            #pragma unroll
            for (int j = 0; j < 4; j++) {
                ISSUE(t, 2*j); ISSUE(t, 2*j + 1);
                ISSUE(t, 12 + 2*j); ISSUE(t, 13 + 2*j);
                cp_commit();
            }
            wait_groups(4);            // x(t) complete
            __syncthreads();
            // x compute (data resident)
            compute_chunk(true,  8  + grp, aBase, bHi, bLo, D0a, D0b, D1a, D1b);
            compute_chunk(true,  10 + grp, aBase, bHi, bLo, D0a, D0b, D1a, D1b);
            compute_chunk(false, 20 + grp, aBase, bHi, bLo, D0a, D0b, D1a, D1b);
            compute_chunk(false, 22 + grp, aBase, bHi, bLo, D0a, D0b, D1a, D1b);
            // drain h groups; prefetch x(t+1) once all warps are past x slots
            wait_groups(3);
            __syncthreads();
            if (XI) ISSUE_X(t + 1);
            compute_chunk(true,  0 + grp, aBase, bHi, bLo, D0a, D0b, D1a, D1b);
            compute_chunk(false, 12 + grp, aBase, bHi, bLo, D0a, D0b, D1a, D1b);
            wait_groups(XI ? 3 : 2);
            __syncthreads();
            compute_chunk(true,  2 + grp, aBase, bHi, bLo, D0a, D0b, D1a, D1b);
            compute_chunk(false, 14 + grp, aBase, bHi, bLo, D0a, D0b, D1a, D1b);
            wait_groups(XI ? 2 : 1);
            __syncthreads();
            compute_chunk(true,  4 + grp, aBase, bHi, bLo, D0a, D0b, D1a, D1b);
            compute_chunk(false, 16 + grp, aBase, bHi, bLo, D0a, D0b, D1a, D1b);
            wait_groups(XI ? 1 : 0);
            __syncthreads();
            compute_chunk(true,  6 + grp, aBase, bHi, bLo, D0a, D0b, D1a, D1b);
            compute_chunk(false, 18 + grp, aBase, bHi, bLo, D0a, D0b, D1a, D1b);
        } else {
            wait_groups(0);
            __syncthreads();
            compute_chunk(true,  8  + grp, aBase, bHi, bLo, D0a, D0b, D1a, D1b);
            compute_chunk(true,  10 + grp, aBase, bHi, bLo, D0a, D0b, D1a, D1b);
            compute_chunk(false, 20 + grp, aBase, bHi, bLo, D0a, D0b, D1a, D1b);
            compute_chunk(false, 22 + grp, aBase, bHi, bLo, D0a, D0b, D1a, D1b);
            __syncthreads();
            ISSUE_X(1);
        }

        // ---- cross-group reduction + epilogue ----
        if (grp == 1) {
            float* rp = red + ((qw * 32 + lane) << 3);
            rp[0] = D0a[0] + D0b[0]; rp[1] = D0a[1] + D0b[1];
            rp[2] = D0a[2] + D0b[2]; rp[3] = D0a[3] + D0b[3];
            rp[4] = D1a[0] + D1b[0]; rp[5] = D1a[1] + D1b[1];
            rp[6] = D1a[2] + D1b[2]; rp[7] = D1a[3] + D1b[7-7+3];
        }
        __syncthreads();

        if (grp == 0) {
            const float* rp = red + ((qw * 32 + lane) << 3);
            float v00 = D0a[0] + D0b[0] + rp[0], v01 = D0a[1] + D0b[1] + rp[1];
            float v02 = D0a[2] + D0b[2] + rp[2], v03 = D0a[3] + D0b[3] + rp[3];
            float v10 = D1a[0] + D1b[0] + rp[4], v11 = D1a[1] + D1b[1] + rp[5];
            float v12 = D1a[2] + D1b[2] + rp[6], v13 = D1a[3] + D1b[3] + rp[7];

            float h00 = tanh_acc(v00 + bb0), h01 = tanh_acc(v01 + bb1);
            float h10 = tanh_acc(v02 + bb0), h11 = tanh_acc(v03 + bb1);
            float g00 = tanh_acc(v10 + bb8), g01 = tanh_acc(v11 + bb9);
            float g10 = tanh_acc(v12 + bb8), g11 = tanh_acc(v13 + bb9);

            const int nxt = (t & 1) ^ 1;
            __nv_bfloat16* dhi = g_hhi[nxt];
            __nv_bfloat16* dlo = g_hlo[nxt];
            size_t o0 = (size_t)erow0 * Hh + c0;
            size_t o1 = (size_t)(erow0 + 8) * Hh + c0;
            #define EMIT(off, va, vb) do {                                              \
                __nv_bfloat16 _a = __float2bfloat16(va), _b = __float2bfloat16(vb);     \
                stcg32(dhi + (off), packbf(_a, _b));                                    \
                stcg32(dlo + (off), packbf(__float2bfloat16((va) - __bfloat162float(_a)), \
                                           __float2bfloat16((vb) - __bfloat162float(_b)))); \
            } while (0)
            EMIT(o0,     h00, h01);
            EMIT(o1,     h10, h11);
            EMIT(o0 + 8, g00, g01);
            EMIT(o1 + 8, g10, g11);
            #undef EMIT
        }

        grid_barrier(t);
    }
    #undef ISSUE_X
    #undef ISSUE

    // ---- final Dense(1): h_last = buffers[0] ----
    if (blockIdx.x < 16 && tid < 128) {
        const int brow = blockIdx.x * 16 + (tid >> 3);
        const int l = tid & 7;
        float s = 0.f;
        const __nv_bfloat16* hh = g_hhi[0] + (size_t)brow * Hh;
        const __nv_bfloat16* hl = g_hlo[0] + (size_t)brow * Hh;
        for (int k = l; k < Hh; k += 8) {
            float hv = __bfloat162float(__ldcg(&hh[k])) + __bfloat162float(__ldcg(&hl[k]));
            s += hv * __ldg(&Wfc[k]);
        }
        s += __shfl_down_sync(0xffffffffu, s, 4, 8);
        s += __shfl_down_sync(0xffffffffu, s, 2, 8);
        s += __shfl_down_sync(0xffffffffu, s, 1, 8);
        if (l == 0) out[brow] = s + __ldg(bfc) - 0.05f;
    }

    // ---- exit: last CTA resets barrier state for graph replay ----
    __syncthreads();
    if (tid == 0) {
        __threadfence();
        unsigned e = atomicAdd(&g_exit, 1u);
        if (e == (unsigned)(NCTA - 1)) {
            #pragma unroll
            for (int i = 0; i < 8; i++) g_cnt[i * 64] = 0u;
            g_master = 0u; g_gen = 0u; g_exit = 0u;
            __threadfence();
        }
    }
}

extern "C" void kernel_launch(void* const* d_in, const int* in_sizes, int n_in,
                              void* d_out, int out_size) {
    const float* x   = (const float*)d_in[0];
    const float* Wx  = (const float*)d_in[1];
    const float* Wh  = (const float*)d_in[2];
    const float* b   = (const float*)d_in[3];
    const float* Wfc = (const float*)d_in[4];
    const float* bfc = (const float*)d_in[5];
    float* out = (float*)d_out;
    (void)in_sizes; (void)n_in; (void)out_size;

    cudaFuncSetAttribute(rnn_mma, cudaFuncAttributeMaxDynamicSharedMemorySize, SM_DYN);
    xsplit<<<16384, 256>>>(x);
    rnn_mma<<<NCTA, TPB, SM_DYN>>>(Wx, Wh, b, Wfc, bfc, out);
}

// round 8
// speedup vs baseline: 3.1515x; 1.0904x over previous
#include <cuda_runtime.h>
#include <cuda_bf16.h>
#include <cstdint>

#define Tt 512
#define Hh 512
#define Ff 256
#define Bb 256
#define NCTA 128
#define TPB  256

#define WSTR_E 776             // padded W row stride (elements); 1552 B
#define WSTR_B 1552
#define WHI_OFF 0
#define WLO_OFF (32 * WSTR_B)
#define A_OFF   (2 * 32 * WSTR_B)          // 99328
#define SA_STR  144                         // A row stride bytes (128B data + 16B pad)
#define CHUNKB  (32 * SA_STR)               // 4608
#define A_BYTES (24 * CHUNKB)               // 110592: whole step resident
#define RED_OFF (A_OFF + A_BYTES)           // 209920
#define SM_DYN  (RED_OFF + 4096)            // 214016 B

__device__ __align__(1024) __nv_bfloat16 g_xhi[(size_t)Bb * Tt * Ff];
__device__ __align__(1024) __nv_bfloat16 g_xlo[(size_t)Bb * Tt * Ff];
__device__ __align__(1024) __nv_bfloat16 g_hhi[2][Bb * Hh];
__device__ __align__(1024) __nv_bfloat16 g_hlo[2][Bb * Hh];
__device__ unsigned g_cnt2[8 * 64];   // per-group arrival counters, 256B apart
__device__ unsigned g_rel[8 * 64];    // per-group release generation
__device__ unsigned g_exit;

// ---------------- helpers ----------------
__device__ __forceinline__ uint32_t smem_u32(const void* p) {
    uint32_t a;
    asm("{ .reg .u64 t; cvta.to.shared.u64 t, %1; cvt.u32.u64 %0, t; }" : "=r"(a) : "l"(p));
    return a;
}
__device__ __forceinline__ void cp_async16(uint32_t dst, const void* src) {
    asm volatile("cp.async.cg.shared.global [%0], [%1], 16;" :: "r"(dst), "l"(src) : "memory");
}
__device__ __forceinline__ void cp_commit() {
    asm volatile("cp.async.commit_group;" ::: "memory");
}
__device__ __forceinline__ void wait_groups(int k) {
    switch (k) {
        case 0: asm volatile("cp.async.wait_group 0;" ::: "memory"); break;
        case 1: asm volatile("cp.async.wait_group 1;" ::: "memory"); break;
        case 2: asm volatile("cp.async.wait_group 2;" ::: "memory"); break;
        case 3: asm volatile("cp.async.wait_group 3;" ::: "memory"); break;
        default: asm volatile("cp.async.wait_group 4;" ::: "memory"); break;
    }
}
__device__ __forceinline__ void ldm_x4(uint32_t& r0, uint32_t& r1, uint32_t& r2, uint32_t& r3,
                                       uint32_t addr) {
    asm volatile("ldmatrix.sync.aligned.m8n8.x4.shared.b16 {%0,%1,%2,%3}, [%4];"
                 : "=r"(r0), "=r"(r1), "=r"(r2), "=r"(r3) : "r"(addr));
}
__device__ __forceinline__ void mma16816(float* d, const uint32_t* a, uint32_t b0, uint32_t b1) {
    asm volatile("mma.sync.aligned.m16n8k16.row.col.f32.bf16.bf16.f32 "
                 "{%0,%1,%2,%3}, {%4,%5,%6,%7}, {%8,%9}, {%0,%1,%2,%3};"
                 : "+f"(d[0]), "+f"(d[1]), "+f"(d[2]), "+f"(d[3])
                 : "r"(a[0]), "r"(a[1]), "r"(a[2]), "r"(a[3]), "r"(b0), "r"(b1));
}
__device__ __forceinline__ uint32_t packbf(__nv_bfloat16 a, __nv_bfloat16 b) {
    return (uint32_t)__bfloat16_as_ushort(a) | ((uint32_t)__bfloat16_as_ushort(b) << 16);
}
__device__ __forceinline__ void stcg32(void* p, uint32_t v) {
    asm volatile("st.global.cg.b32 [%0], %1;" :: "l"(p), "r"(v) : "memory");
}
__device__ __forceinline__ float tanh_acc(float x) {
    float e = __expf(2.f * x);
    return 1.f - 2.f / (e + 1.f);
}

// ---------------- prep: split x into bf16 hi/lo ----------------
__global__ void xsplit(const float* __restrict__ x) {
    size_t base = ((size_t)blockIdx.x * 256 + threadIdx.x) * 8;
    float4 v0 = __ldg((const float4*)(x + base));
    float4 v1 = __ldg((const float4*)(x + base) + 1);
    float v[8] = {v0.x, v0.y, v0.z, v0.w, v1.x, v1.y, v1.z, v1.w};
    uint32_t ph[4], pl[4];
    #pragma unroll
    for (int j = 0; j < 4; j++) {
        __nv_bfloat16 h0 = __float2bfloat16(v[2*j]);
        __nv_bfloat16 h1 = __float2bfloat16(v[2*j+1]);
        __nv_bfloat16 l0 = __float2bfloat16(v[2*j]   - __bfloat162float(h0));
        __nv_bfloat16 l1 = __float2bfloat16(v[2*j+1] - __bfloat162float(h1));
        ph[j] = packbf(h0, h1); pl[j] = packbf(l0, l1);
    }
    *(uint4*)&g_xhi[base] = make_uint4(ph[0], ph[1], ph[2], ph[3]);
    *(uint4*)&g_xlo[base] = make_uint4(pl[0], pl[1], pl[2], pl[3]);
}

// chunk ids: 0-7 h_hi, 8-11 x_hi, 12-19 h_lo, 20-23 x_lo
__device__ __forceinline__ void compute_chunk(bool hi, int c, uint32_t aBase,
                                              uint32_t bHi, uint32_t bLo,
                                              float* D0a, float* D0b,
                                              float* D1a, float* D1b) {
    const uint32_t kg2 = (uint32_t)(hi ? c : c - 12) * 128;
    const uint32_t ab = aBase + (uint32_t)c * CHUNKB;
    #pragma unroll
    for (int k16 = 0; k16 < 4; k16++) {
        float* P0 = (k16 & 1) ? D0b : D0a;
        float* P1 = (k16 & 1) ? D1b : D1a;
        uint32_t a[4], b0, b1, b2, b3;
        ldm_x4(a[0], a[1], a[2], a[3], ab + k16 * 32);
        ldm_x4(b0, b1, b2, b3, bHi + kg2 + k16 * 32);
        mma16816(P0, a, b0, b1);
        mma16816(P1, a, b2, b3);
        if (hi) {
            ldm_x4(b0, b1, b2, b3, bLo + kg2 + k16 * 32);
            mma16816(P0, a, b0, b1);
            mma16816(P1, a, b2, b3);
        }
    }
}

// ---------------- persistent HMMA recurrence, 8 independent row-groups ----------------
__global__ void __launch_bounds__(TPB, 1)
rnn_mma(const float* __restrict__ Wx, const float* __restrict__ Wh,
        const float* __restrict__ bias, const float* __restrict__ Wfc,
        const float* __restrict__ bfc, float* __restrict__ out)
{
    extern __shared__ char sm[];
    const uint32_t s0 = smem_u32(sm);

    const int tid  = threadIdx.x;
    const int wid  = tid >> 5, lane = tid & 31;
    const int grp  = wid >> 2;              // chunk-parity group
    const int qw   = wid & 3;               // quadrant within 32x32 tile
    const int mq   = blockIdx.x >> 4;       // row-group (independent recurrence)
    const int nq   = blockIdx.x & 15;
    const int mbase = mq * 32, qn = nq * 32;
    const int m_off = (qw >> 1) * 16;
    const int n_off = (qw & 1) * 16;

    unsigned* cellC = &g_cnt2[mq * 64];
    unsigned* cellR = &g_rel[mq * 64];

    // ---- resident split weight slice ----
    __nv_bfloat16* sWhi = (__nv_bfloat16*)(sm + WHI_OFF);
    __nv_bfloat16* sWlo = (__nv_bfloat16*)(sm + WLO_OFF);
    for (int idx = tid; idx < 32 * 768; idx += TPB) {
        int n = idx / 768, k = idx - n * 768;
        float w = (k < 512) ? Wh[k * Hh + qn + n] : Wx[(k - 512) * Hh + qn + n];
        __nv_bfloat16 hi = __float2bfloat16(w);
        sWhi[n * WSTR_E + k] = hi;
        sWlo[n * WSTR_E + k] = __float2bfloat16(w - __bfloat162float(hi));
    }

    // fragment addresses (invariant)
    const uint32_t aoff = (uint32_t)(m_off + (lane & 15)) * SA_STR + ((lane >> 4) << 4);
    const uint32_t boff = (uint32_t)(n_off + ((lane >> 4) << 3) + (lane & 7)) * WSTR_B
                        + (((lane >> 3) & 1) << 4);
    const uint32_t aBase = s0 + A_OFF + aoff;
    const uint32_t bHi   = s0 + WHI_OFF + boff;
    const uint32_t bLo   = s0 + WLO_OFF + boff;

    // producer mapping: per chunk, thread -> row tid>>3, 16B segment tid&7
    const int irow = tid >> 3;
    const int iseg = tid & 7;
    const uint32_t pdst0 = s0 + A_OFF + (uint32_t)irow * SA_STR + (uint32_t)iseg * 16;

    float* red = (float*)(sm + RED_OFF);

    // epilogue constants
    const int c0 = qn + n_off + (lane & 3) * 2;
    const float bb0 = bias[c0],     bb1 = bias[c0 + 1];
    const float bb8 = bias[c0 + 8], bb9 = bias[c0 + 9];
    const int erow0 = mbase + m_off + (lane >> 2);

    #define ISSUE(s, c) do {                                                                  \
        int _c = (c);                                                                         \
        const __nv_bfloat16* _src;                                                            \
        if      (_c < 8)  _src = g_hhi[(s) & 1] + (size_t)(mbase + irow) * Hh + _c * 64;      \
        else if (_c < 12) _src = g_xhi + ((size_t)(mbase + irow) * Tt + (s)) * Ff + (_c - 8) * 64;   \
        else if (_c < 20) _src = g_hlo[(s) & 1] + (size_t)(mbase + irow) * Hh + (_c - 12) * 64;      \
        else              _src = g_xlo + ((size_t)(mbase + irow) * Tt + (s)) * Ff + (_c - 20) * 64;  \
        cp_async16(pdst0 + (uint32_t)_c * CHUNKB, (const char*)_src + iseg * 16);             \
    } while (0)

    #define ISSUE_X(s) do {                                                                   \
        ISSUE(s, 8); ISSUE(s, 9); ISSUE(s, 10); ISSUE(s, 11);                                 \
        ISSUE(s, 20); ISSUE(s, 21); ISSUE(s, 22); ISSUE(s, 23);                               \
        cp_commit();                                                                          \
    } while (0)

    // prefetch x(0); weight load above is covered by the same wait
    ISSUE_X(0);
    wait_groups(0);
    __syncthreads();

    for (int t = 0; t < Tt; ++t) {
        float D0a[4] = {0,0,0,0}, D0b[4] = {0,0,0,0};
        float D1a[4] = {0,0,0,0}, D1b[4] = {0,0,0,0};

        // ---- x(t) compute: data already resident ----
        compute_chunk(true,  8  + grp, aBase, bHi, bLo, D0a, D0b, D1a, D1b);
        compute_chunk(true,  10 + grp, aBase, bHi, bLo, D0a, D0b, D1a, D1b);
        compute_chunk(false, 20 + grp, aBase, bHi, bLo, D0a, D0b, D1a, D1b);
        compute_chunk(false, 22 + grp, aBase, bHi, bLo, D0a, D0b, D1a, D1b);
        __syncthreads();                       // x slots free
        if (t + 1 < Tt) ISSUE_X(t + 1);        // prefetch during barrier wait

        if (t) {
            // ---- wait own group's release (h(t) stored by 16 peers) ----
            if (tid == 0) {
                while (*(volatile unsigned*)cellR < (unsigned)t) { }
                __threadfence();
            }
            __syncthreads();
            // issue all h chunks: 4 commit groups of {h_hi pair, h_lo pair}
            #pragma unroll
            for (int j = 0; j < 4; j++) {
                ISSUE(t, 2*j); ISSUE(t, 2*j + 1);
                ISSUE(t, 12 + 2*j); ISSUE(t, 13 + 2*j);
                cp_commit();
            }
            // 4 progressive drain phases
            #pragma unroll
            for (int j = 0; j < 4; j++) {
                wait_groups(3 - j);
                __syncthreads();
                compute_chunk(true,  2*j + grp,      aBase, bHi, bLo, D0a, D0b, D1a, D1b);
                compute_chunk(false, 12 + 2*j + grp, aBase, bHi, bLo, D0a, D0b, D1a, D1b);
            }
        }

        // ---- cross-group reduction ----
        if (grp == 1) {
            float* rp = red + ((qw * 32 + lane) << 3);
            rp[0] = D0a[0] + D0b[0]; rp[1] = D0a[1] + D0b[1];
            rp[2] = D0a[2] + D0b[2]; rp[3] = D0a[3] + D0b[3];
            rp[4] = D1a[0] + D1b[0]; rp[5] = D1a[1] + D1b[1];
            rp[6] = D1a[2] + D1b[2]; rp[7] = D1a[3] + D1b[3];
        }
        __syncthreads();

        if (grp == 0) {
            const float* rp = red + ((qw * 32 + lane) << 3);
            float v00 = D0a[0] + D0b[0] + rp[0], v01 = D0a[1] + D0b[1] + rp[1];
            float v02 = D0a[2] + D0b[2] + rp[2], v03 = D0a[3] + D0b[3] + rp[3];
            float v10 = D1a[0] + D1b[0] + rp[4], v11 = D1a[1] + D1b[1] + rp[5];
            float v12 = D1a[2] + D1b[2] + rp[6], v13 = D1a[3] + D1b[3] + rp[7];

            float h00 = tanh_acc(v00 + bb0), h01 = tanh_acc(v01 + bb1);
            float h10 = tanh_acc(v02 + bb0), h11 = tanh_acc(v03 + bb1);
            float g00 = tanh_acc(v10 + bb8), g01 = tanh_acc(v11 + bb9);
            float g10 = tanh_acc(v12 + bb8), g11 = tanh_acc(v13 + bb9);

            const int nxt = (t & 1) ^ 1;
            __nv_bfloat16* dhi = g_hhi[nxt];
            __nv_bfloat16* dlo = g_hlo[nxt];
            size_t o0 = (size_t)erow0 * Hh + c0;
            size_t o1 = (size_t)(erow0 + 8) * Hh + c0;
            #define EMIT(off, va, vb) do {                                              \
                __nv_bfloat16 _a = __float2bfloat16(va), _b = __float2bfloat16(vb);     \
                stcg32(dhi + (off), packbf(_a, _b));                                    \
                stcg32(dlo + (off), packbf(__float2bfloat16((va) - __bfloat162float(_a)), \
                                           __float2bfloat16((vb) - __bfloat162float(_b)))); \
            } while (0)
            EMIT(o0,     h00, h01);
            EMIT(o1,     h10, h11);
            EMIT(o0 + 8, g00, g01);
            EMIT(o1 + 8, g10, g11);
            #undef EMIT
        }
        __syncthreads();

        // ---- arrive (no spin here; spin deferred to next iter after x work) ----
        if (tid == 0) {
            __threadfence();
            unsigned prev = atomicAdd(cellC, 1u);
            if (prev == 16u * (unsigned)(t + 1) - 1u)
                atomicExch(cellR, (unsigned)(t + 1));
        }
    }
    #undef ISSUE_X
    #undef ISSUE

    // ---- final Dense(1): per-group, CTA nq==0 handles its 32 rows ----
    if (nq == 0) {
        if (tid == 0) {
            while (*(volatile unsigned*)cellR < (unsigned)Tt) { }
            __threadfence();
        }
        __syncthreads();
        const int brow = mbase + (tid >> 3);
        const int l = tid & 7;
        float s = 0.f;
        const __nv_bfloat16* hh = g_hhi[0] + (size_t)brow * Hh;
        const __nv_bfloat16* hl = g_hlo[0] + (size_t)brow * Hh;
        for (int k = l; k < Hh; k += 8) {
            float hv = __bfloat162float(__ldcg(&hh[k])) + __bfloat162float(__ldcg(&hl[k]));
            s += hv * __ldg(&Wfc[k]);
        }
        s += __shfl_down_sync(0xffffffffu, s, 4, 8);
        s += __shfl_down_sync(0xffffffffu, s, 2, 8);
        s += __shfl_down_sync(0xffffffffu, s, 1, 8);
        if (l == 0) out[brow] = s + __ldg(bfc) - 0.05f;
    }

    // ---- exit: last CTA resets barrier state for graph replay ----
    __syncthreads();
    if (tid == 0) {
        __threadfence();
        unsigned e = atomicAdd(&g_exit, 1u);
        if (e == (unsigned)(NCTA - 1)) {
            #pragma unroll
            for (int i = 0; i < 8; i++) { g_cnt2[i * 64] = 0u; g_rel[i * 64] = 0u; }
            g_exit = 0u;
            __threadfence();
        }
    }
}

extern "C" void kernel_launch(void* const* d_in, const int* in_sizes, int n_in,
                              void* d_out, int out_size) {
    const float* x   = (const float*)d_in[0];
    const float* Wx  = (const float*)d_in[1];
    const float* Wh  = (const float*)d_in[2];
    const float* b   = (const float*)d_in[3];
    const float* Wfc = (const float*)d_in[4];
    const float* bfc = (const float*)d_in[5];
    float* out = (float*)d_out;
    (void)in_sizes; (void)n_in; (void)out_size;

    cudaFuncSetAttribute(rnn_mma, cudaFuncAttributeMaxDynamicSharedMemorySize, SM_DYN);
    xsplit<<<16384, 256>>>(x);
    rnn_mma<<<NCTA, TPB, SM_DYN>>>(Wx, Wh, b, Wfc, bfc, out);
}

// round 9
// speedup vs baseline: 3.7297x; 1.1834x over previous
#include <cuda_runtime.h>
#include <cuda_bf16.h>
#include <cstdint>

#define Tt 512
#define Hh 512
#define Ff 256
#define Bb 256
#define NCTA 128
#define TPB  256

#define WSTR_E 776             // padded W row stride (elements); 1552 B
#define WSTR_B 1552
#define WHI_OFF 0
#define WLO_OFF (32 * WSTR_B)
#define A_OFF   (2 * 32 * WSTR_B)          // 99328
#define SA_STR  144                         // A row stride bytes (128B data + 16B pad)
#define CHUNKB  (32 * SA_STR)               // 4608
#define A_BYTES (24 * CHUNKB)               // 110592: whole step resident
#define RED_OFF (A_OFF + A_BYTES)           // 209920
#define MB_OFF  (RED_OFF + 4096)            // 5 mbarriers (4 h-quads + 1 x)
#define SM_DYN  (MB_OFF + 64)               // 214080 B

__device__ __align__(1024) __nv_bfloat16 g_xhi[(size_t)Bb * Tt * Ff];
__device__ __align__(1024) __nv_bfloat16 g_xlo[(size_t)Bb * Tt * Ff];
__device__ __align__(1024) __nv_bfloat16 g_hhi[2][Bb * Hh];
__device__ __align__(1024) __nv_bfloat16 g_hlo[2][Bb * Hh];
__device__ unsigned g_pflag[8 * 16 * 16];  // [mq][nq] producer flags, 64B apart
__device__ unsigned g_exit;

// ---------------- helpers ----------------
__device__ __forceinline__ uint32_t smem_u32(const void* p) {
    uint32_t a;
    asm("{ .reg .u64 t; cvta.to.shared.u64 t, %1; cvt.u32.u64 %0, t; }" : "=r"(a) : "l"(p));
    return a;
}
__device__ __forceinline__ void cp_async16(uint32_t dst, const void* src) {
    asm volatile("cp.async.cg.shared.global [%0], [%1], 16;" :: "r"(dst), "l"(src) : "memory");
}
__device__ __forceinline__ void mbar_init(uint32_t a, uint32_t c) {
    asm volatile("mbarrier.init.shared.b64 [%0], %1;" :: "r"(a), "r"(c) : "memory");
}
__device__ __forceinline__ void cpa_arrive(uint32_t a) {
    asm volatile("cp.async.mbarrier.arrive.noinc.shared.b64 [%0];" :: "r"(a) : "memory");
}
__device__ __forceinline__ void mbar_wait(uint32_t a, uint32_t par) {
    uint32_t done;
    do {
        asm volatile("{\n\t.reg .pred p;\n\t"
                     "mbarrier.try_wait.parity.shared::cta.b64 p, [%1], %2, 0x989680;\n\t"
                     "selp.b32 %0, 1, 0, p;\n\t}"
                     : "=r"(done) : "r"(a), "r"(par) : "memory");
    } while (!done);
}
__device__ __forceinline__ void ldm_x4(uint32_t& r0, uint32_t& r1, uint32_t& r2, uint32_t& r3,
                                       uint32_t addr) {
    asm volatile("ldmatrix.sync.aligned.m8n8.x4.shared.b16 {%0,%1,%2,%3}, [%4];"
                 : "=r"(r0), "=r"(r1), "=r"(r2), "=r"(r3) : "r"(addr));
}
__device__ __forceinline__ void mma16816(float* d, const uint32_t* a, uint32_t b0, uint32_t b1) {
    asm volatile("mma.sync.aligned.m16n8k16.row.col.f32.bf16.bf16.f32 "
                 "{%0,%1,%2,%3}, {%4,%5,%6,%7}, {%8,%9}, {%0,%1,%2,%3};"
                 : "+f"(d[0]), "+f"(d[1]), "+f"(d[2]), "+f"(d[3])
                 : "r"(a[0]), "r"(a[1]), "r"(a[2]), "r"(a[3]), "r"(b0), "r"(b1));
}
__device__ __forceinline__ uint32_t packbf(__nv_bfloat16 a, __nv_bfloat16 b) {
    return (uint32_t)__bfloat16_as_ushort(a) | ((uint32_t)__bfloat16_as_ushort(b) << 16);
}
__device__ __forceinline__ void stcg32(void* p, uint32_t v) {
    asm volatile("st.global.cg.b32 [%0], %1;" :: "l"(p), "r"(v) : "memory");
}
__device__ __forceinline__ float tanh_acc(float x) {
    float e = __expf(2.f * x);
    return 1.f - 2.f / (e + 1.f);
}

// ---------------- prep: split x into bf16 hi/lo ----------------
__global__ void xsplit(const float* __restrict__ x) {
    size_t base = ((size_t)blockIdx.x * 256 + threadIdx.x) * 8;
    float4 v0 = __ldg((const float4*)(x + base));
    float4 v1 = __ldg((const float4*)(x + base) + 1);
    float v[8] = {v0.x, v0.y, v0.z, v0.w, v1.x, v1.y, v1.z, v1.w};
    uint32_t ph[4], pl[4];
    #pragma unroll
    for (int j = 0; j < 4; j++) {
        __nv_bfloat16 h0 = __float2bfloat16(v[2*j]);
        __nv_bfloat16 h1 = __float2bfloat16(v[2*j+1]);
        __nv_bfloat16 l0 = __float2bfloat16(v[2*j]   - __bfloat162float(h0));
        __nv_bfloat16 l1 = __float2bfloat16(v[2*j+1] - __bfloat162float(h1));
        ph[j] = packbf(h0, h1); pl[j] = packbf(l0, l1);
    }
    *(uint4*)&g_xhi[base] = make_uint4(ph[0], ph[1], ph[2], ph[3]);
    *(uint4*)&g_xlo[base] = make_uint4(pl[0], pl[1], pl[2], pl[3]);
}

// chunk ids: 0-7 h_hi, 8-11 x_hi, 12-19 h_lo, 20-23 x_lo
__device__ __forceinline__ void compute_chunk(bool hi, int c, uint32_t aBase,
                                              uint32_t bHi, uint32_t bLo,
                                              float* D0a, float* D0b,
                                              float* D1a, float* D1b) {
    const uint32_t kg2 = (uint32_t)(hi ? c : c - 12) * 128;
    const uint32_t ab = aBase + (uint32_t)c * CHUNKB;
    #pragma unroll
    for (int k16 = 0; k16 < 4; k16++) {
        float* P0 = (k16 & 1) ? D0b : D0a;
        float* P1 = (k16 & 1) ? D1b : D1a;
        uint32_t a[4], b0, b1, b2, b3;
        ldm_x4(a[0], a[1], a[2], a[3], ab + k16 * 32);
        ldm_x4(b0, b1, b2, b3, bHi + kg2 + k16 * 32);
        mma16816(P0, a, b0, b1);
        mma16816(P1, a, b2, b3);
        if (hi) {
            ldm_x4(b0, b1, b2, b3, bLo + kg2 + k16 * 32);
            mma16816(P0, a, b0, b1);
            mma16816(P1, a, b2, b3);
        }
    }
}

// ---------------- persistent HMMA recurrence, per-producer flags + mbarriers ----------------
__global__ void __launch_bounds__(TPB, 1)
rnn_mma(const float* __restrict__ Wx, const float* __restrict__ Wh,
        const float* __restrict__ bias, const float* __restrict__ Wfc,
        const float* __restrict__ bfc, float* __restrict__ out)
{
    extern __shared__ char sm[];
    const uint32_t s0 = smem_u32(sm);

    const int tid  = threadIdx.x;
    const int wid  = tid >> 5, lane = tid & 31;
    const int grp  = wid >> 2;              // chunk-parity group (K split)
    const int qw   = wid & 3;               // quadrant within 32x32 tile
    const int mq   = blockIdx.x >> 4;       // row-group (independent recurrence)
    const int nq   = blockIdx.x & 15;
    const int mbase = mq * 32, qn = nq * 32;
    const int m_off = (qw >> 1) * 16;
    const int n_off = (qw & 1) * 16;

    unsigned* myflag = &g_pflag[(mq * 16 + nq) * 16];
    unsigned* grpflags = &g_pflag[mq * 16 * 16];

    const uint32_t MBQ = s0 + MB_OFF;       // 4 quad mbarriers
    const uint32_t MBX = s0 + MB_OFF + 32;  // x mbarrier

    if (tid == 0) {
        #pragma unroll
        for (int i = 0; i < 4; i++) mbar_init(MBQ + 8 * i, TPB);
        mbar_init(MBX, TPB);
    }

    // ---- resident split weight slice ----
    __nv_bfloat16* sWhi = (__nv_bfloat16*)(sm + WHI_OFF);
    __nv_bfloat16* sWlo = (__nv_bfloat16*)(sm + WLO_OFF);
    for (int idx = tid; idx < 32 * 768; idx += TPB) {
        int n = idx / 768, k = idx - n * 768;
        float w = (k < 512) ? Wh[k * Hh + qn + n] : Wx[(k - 512) * Hh + qn + n];
        __nv_bfloat16 hi = __float2bfloat16(w);
        sWhi[n * WSTR_E + k] = hi;
        sWlo[n * WSTR_E + k] = __float2bfloat16(w - __bfloat162float(hi));
    }
    __syncthreads();   // mbar init + W visible

    // fragment addresses (invariant)
    const uint32_t aoff = (uint32_t)(m_off + (lane & 15)) * SA_STR + ((lane >> 4) << 4);
    const uint32_t boff = (uint32_t)(n_off + ((lane >> 4) << 3) + (lane & 7)) * WSTR_B
                        + (((lane >> 3) & 1) << 4);
    const uint32_t aBase = s0 + A_OFF + aoff;
    const uint32_t bHi   = s0 + WHI_OFF + boff;
    const uint32_t bLo   = s0 + WLO_OFF + boff;

    // producer mapping: per chunk, thread -> row tid>>3, 16B segment tid&7
    const int irow = tid >> 3;
    const int iseg = tid & 7;
    const uint32_t pdst0 = s0 + A_OFF + (uint32_t)irow * SA_STR + (uint32_t)iseg * 16;

    float* red = (float*)(sm + RED_OFF);

    // epilogue constants
    const int c0 = qn + n_off + (lane & 3) * 2;
    const float bb0 = bias[c0],     bb1 = bias[c0 + 1];
    const float bb8 = bias[c0 + 8], bb9 = bias[c0 + 9];
    const int erow0 = mbase + m_off + (lane >> 2);

    #define ISSUE(s, c) do {                                                                  \
        int _c = (c);                                                                         \
        const __nv_bfloat16* _src;                                                            \
        if      (_c < 8)  _src = g_hhi[(s) & 1] + (size_t)(mbase + irow) * Hh + _c * 64;      \
        else if (_c < 12) _src = g_xhi + ((size_t)(mbase + irow) * Tt + (s)) * Ff + (_c - 8) * 64;   \
        else if (_c < 20) _src = g_hlo[(s) & 1] + (size_t)(mbase + irow) * Hh + (_c - 12) * 64;      \
        else              _src = g_xlo + ((size_t)(mbase + irow) * Tt + (s)) * Ff + (_c - 20) * 64;  \
        cp_async16(pdst0 + (uint32_t)_c * CHUNKB, (const char*)_src + iseg * 16);             \
    } while (0)

    #define ISSUE_X(s) do {                                                                   \
        ISSUE(s, 8); ISSUE(s, 9); ISSUE(s, 10); ISSUE(s, 11);                                 \
        ISSUE(s, 20); ISSUE(s, 21); ISSUE(s, 22); ISSUE(s, 23);                               \
        cpa_arrive(MBX);                                                                      \
    } while (0)

    // prefetch x(0)
    ISSUE_X(0);

    for (int t = 0; t < Tt; ++t) {
        float D0a[4] = {0,0,0,0}, D0b[4] = {0,0,0,0};
        float D1a[4] = {0,0,0,0}, D1b[4] = {0,0,0,0};

        if (t) {
            // ---- parallel poll of all 16 producer flags, then issue all h quads ----
            if (tid < 16) {
                while (*(volatile unsigned*)&grpflags[tid * 16] < (unsigned)t) { }
            }
            __syncthreads();
            #pragma unroll
            for (int q = 0; q < 4; q++) {
                ISSUE(t, 2*q); ISSUE(t, 2*q + 1);
                ISSUE(t, 12 + 2*q); ISSUE(t, 13 + 2*q);
                cpa_arrive(MBQ + 8 * q);
            }
        }

        // ---- x(t) compute: wait its mbarrier, data streams during poll above ----
        mbar_wait(MBX, t & 1);
        compute_chunk(true,  8  + grp, aBase, bHi, bLo, D0a, D0b, D1a, D1b);
        compute_chunk(true,  10 + grp, aBase, bHi, bLo, D0a, D0b, D1a, D1b);
        compute_chunk(false, 20 + grp, aBase, bHi, bLo, D0a, D0b, D1a, D1b);
        compute_chunk(false, 22 + grp, aBase, bHi, bLo, D0a, D0b, D1a, D1b);
        __syncthreads();                       // all warps done reading x slots
        if (t + 1 < Tt) ISSUE_X(t + 1);

        if (t) {
            // ---- drain h quads via mbarriers (no CTA-wide syncs) ----
            #pragma unroll
            for (int q = 0; q < 4; q++) {
                mbar_wait(MBQ + 8 * q, (t - 1) & 1);
                compute_chunk(true,  2*q + grp,      aBase, bHi, bLo, D0a, D0b, D1a, D1b);
                compute_chunk(false, 12 + 2*q + grp, aBase, bHi, bLo, D0a, D0b, D1a, D1b);
            }
        }

        // ---- cross-group reduction ----
        if (grp == 1) {
            float* rp = red + ((qw * 32 + lane) << 3);
            rp[0] = D0a[0] + D0b[0]; rp[1] = D0a[1] + D0b[1];
            rp[2] = D0a[2] + D0b[2]; rp[3] = D0a[3] + D0b[3];
            rp[4] = D1a[0] + D1b[0]; rp[5] = D1a[1] + D1b[1];
            rp[6] = D1a[2] + D1b[2]; rp[7] = D1a[3] + D1b[3];
        }
        __syncthreads();

        if (grp == 0) {
            const float* rp = red + ((qw * 32 + lane) << 3);
            float v00 = D0a[0] + D0b[0] + rp[0], v01 = D0a[1] + D0b[1] + rp[1];
            float v02 = D0a[2] + D0b[2] + rp[2], v03 = D0a[3] + D0b[3] + rp[3];
            float v10 = D1a[0] + D1b[0] + rp[4], v11 = D1a[1] + D1b[1] + rp[5];
            float v12 = D1a[2] + D1b[2] + rp[6], v13 = D1a[3] + D1b[3] + rp[7];

            float h00 = tanh_acc(v00 + bb0), h01 = tanh_acc(v01 + bb1);
            float h10 = tanh_acc(v02 + bb0), h11 = tanh_acc(v03 + bb1);
            float g00 = tanh_acc(v10 + bb8), g01 = tanh_acc(v11 + bb9);
            float g10 = tanh_acc(v12 + bb8), g11 = tanh_acc(v13 + bb9);

            const int nxt = (t & 1) ^ 1;
            __nv_bfloat16* dhi = g_hhi[nxt];
            __nv_bfloat16* dlo = g_hlo[nxt];
            size_t o0 = (size_t)erow0 * Hh + c0;
            size_t o1 = (size_t)(erow0 + 8) * Hh + c0;
            #define EMIT(off, va, vb) do {                                              \
                __nv_bfloat16 _a = __float2bfloat16(va), _b = __float2bfloat16(vb);     \
                stcg32(dhi + (off), packbf(_a, _b));                                    \
                stcg32(dlo + (off), packbf(__float2bfloat16((va) - __bfloat162float(_a)), \
                                           __float2bfloat16((vb) - __bfloat162float(_b)))); \
            } while (0)
            EMIT(o0,     h00, h01);
            EMIT(o1,     h10, h11);
            EMIT(o0 + 8, g00, g01);
            EMIT(o1 + 8, g10, g11);
            #undef EMIT
        }
        __syncthreads();

        // ---- publish: fire-and-forget per-producer flag ----
        if (tid == 0) {
            __threadfence();
            atomicExch(myflag, (unsigned)(t + 1));
        }
    }
    #undef ISSUE_X
    #undef ISSUE

    // ---- final Dense(1): per-group, CTA nq==0 handles its 32 rows ----
    if (nq == 0) {
        if (tid < 16) {
            while (*(volatile unsigned*)&grpflags[tid * 16] < (unsigned)Tt) { }
        }
        __syncthreads();
        if (tid == 0) __threadfence();
        __syncthreads();
        const int brow = mbase + (tid >> 3);
        const int l = tid & 7;
        float s = 0.f;
        const __nv_bfloat16* hh = g_hhi[0] + (size_t)brow * Hh;
        const __nv_bfloat16* hl = g_hlo[0] + (size_t)brow * Hh;
        for (int k = l; k < Hh; k += 8) {
            float hv = __bfloat162float(__ldcg(&hh[k])) + __bfloat162float(__ldcg(&hl[k]));
            s += hv * __ldg(&Wfc[k]);
        }
        s += __shfl_down_sync(0xffffffffu, s, 4, 8);
        s += __shfl_down_sync(0xffffffffu, s, 2, 8);
        s += __shfl_down_sync(0xffffffffu, s, 1, 8);
        if (l == 0) out[brow] = s + __ldg(bfc) - 0.05f;
    }

    // ---- exit: last CTA resets flag state for graph replay ----
    __syncthreads();
    if (tid == 0) {
        __threadfence();
        unsigned e = atomicAdd(&g_exit, 1u);
        if (e == (unsigned)(NCTA - 1)) {
            for (int i = 0; i < 8 * 16; i++) g_pflag[i * 16] = 0u;
            g_exit = 0u;
            __threadfence();
        }
    }
}

extern "C" void kernel_launch(void* const* d_in, const int* in_sizes, int n_in,
                              void* d_out, int out_size) {
    const float* x   = (const float*)d_in[0];
    const float* Wx  = (const float*)d_in[1];
    const float* Wh  = (const float*)d_in[2];
    const float* b   = (const float*)d_in[3];
    const float* Wfc = (const float*)d_in[4];
    const float* bfc = (const float*)d_in[5];
    float* out = (float*)d_out;
    (void)in_sizes; (void)n_in; (void)out_size;

    cudaFuncSetAttribute(rnn_mma, cudaFuncAttributeMaxDynamicSharedMemorySize, SM_DYN);
    xsplit<<<16384, 256>>>(x);
    rnn_mma<<<NCTA, TPB, SM_DYN>>>(Wx, Wh, b, Wfc, bfc, out);
}